// round 1
// baseline (speedup 1.0000x reference)
#include <cuda_runtime.h>
#include <cuda_bf16.h>
#include <math.h>

// Problem constants
#define BB 2
#define CC 256
#define HH 120
#define WW 240
#define SS (HH*WW)          // 28800
#define HID 512
#define KCAT 768            // h0 | hilbert(h0) | x

// ---------------------------------------------------------------------------
// Static scratch (no dynamic allocation allowed)
// ---------------------------------------------------------------------------
__device__ float g_cat  [(size_t)BB*KCAT*SS];  // [B][768][S]: h0 | g | x
__device__ float g_t0   [(size_t)BB*CC*SS];    // post GEMM1+GELU
__device__ float g_t1   [(size_t)BB*CC*SS];    // post norm1+FiLM
__device__ float g_u    [(size_t)BB*HID*SS];   // post mlp1+GELU
__device__ float g_wcat [CC*KCAT];             // packed [256 x 768] weight
__device__ float g_mean0[BB*CC];
__device__ float g_rstd0[BB*CC];
__device__ float g_mean1[BB*CC];
__device__ float g_rstd1[BB*CC];
__device__ float g_scale[BB*CC];
__device__ float g_shift[BB*CC];

// ---------------------------------------------------------------------------
// Pack Wcat[o][k]:  k<256: w_spec_r[k,o] ; k<512: w_spec_i[k-256,o] ; else inner_w[o,k-512]
// ---------------------------------------------------------------------------
__global__ void pack_weights(const float* __restrict__ wr,
                             const float* __restrict__ wi,
                             const float* __restrict__ iw) {
    int idx = blockIdx.x * blockDim.x + threadIdx.x;
    if (idx >= CC * KCAT) return;
    int o = idx / KCAT;
    int k = idx % KCAT;
    float v;
    if (k < 256)        v = wr[k * CC + o];
    else if (k < 512)   v = wi[(k - 256) * CC + o];
    else                v = iw[o * CC + (k - 512)];
    g_wcat[idx] = v;
}

// ---------------------------------------------------------------------------
// InstanceNorm statistics: one block per (b,c)
// ---------------------------------------------------------------------------
__global__ void inorm_stats(const float* __restrict__ x,
                            float* __restrict__ mean, float* __restrict__ rstd) {
    __shared__ float ssum[256];
    __shared__ float ssq[256];
    int bc = blockIdx.x;
    const float* p = x + (size_t)bc * SS;
    int t = threadIdx.x;
    float s = 0.f, q = 0.f;
    for (int i = t; i < SS; i += 256) {
        float v = p[i];
        s += v; q += v * v;
    }
    ssum[t] = s; ssq[t] = q;
    __syncthreads();
    for (int off = 128; off > 0; off >>= 1) {
        if (t < off) { ssum[t] += ssum[t + off]; ssq[t] += ssq[t + off]; }
        __syncthreads();
    }
    if (t == 0) {
        float m = ssum[0] * (1.0f / SS);
        float var = ssq[0] * (1.0f / SS) - m * m;
        mean[bc] = m;
        rstd[bc] = rsqrtf(var + 1e-5f);
    }
}

// ---------------------------------------------------------------------------
// Write h0 = inorm0(x) into cat section 0, copy x into cat section 2 (float4)
// ---------------------------------------------------------------------------
__global__ void prep_cat(const float* __restrict__ x,
                         const float* __restrict__ n0w, const float* __restrict__ n0b) {
    int i4 = blockIdx.x * blockDim.x + threadIdx.x;       // 0 .. B*C*S/4
    if (i4 >= (BB * CC * SS) / 4) return;
    int i = i4 * 4;
    int bc = i / SS;
    int s  = i % SS;
    int b = bc >> 8;
    int c = bc & 255;
    float4 v = ((const float4*)x)[i4];
    float m = g_mean0[bc], r = g_rstd0[bc];
    float w = n0w[c], bb = n0b[c];
    float sc = r * w;
    float sh = -m * r * w + bb;
    float4 h;
    h.x = v.x * sc + sh; h.y = v.y * sc + sh;
    h.z = v.z * sc + sh; h.w = v.w * sc + sh;
    size_t base0 = ((size_t)b * KCAT + c)       * SS + s;
    size_t base2 = ((size_t)b * KCAT + 512 + c) * SS + s;
    *(float4*)&g_cat[base0] = h;
    *(float4*)&g_cat[base2] = v;
}

// ---------------------------------------------------------------------------
// Hilbert-like circular conv along W: g[w] = sum_{d odd} a[d]*h0[(w-d) mod 240]
// a[d] = -(1/120)*cot(pi*d/240) for odd d, 0 for even d.
// One block (240 threads) per (b,c,h) row.  Section0 -> Section1 of g_cat.
// ---------------------------------------------------------------------------
__global__ void hilbert_rows() {
    __shared__ float row[WW];
    __shared__ float ac[WW / 2];
    int r = blockIdx.x;                    // 0 .. B*C*H-1
    int b   = r / (CC * HH);
    int rem = r % (CC * HH);
    int c = rem / HH;
    int h = rem % HH;
    size_t sbase = ((size_t)b * KCAT + c)       * SS + (size_t)h * WW;
    size_t dbase = ((size_t)b * KCAT + 256 + c) * SS + (size_t)h * WW;
    int t = threadIdx.x;                   // 0..239
    row[t] = g_cat[sbase + t];
    if (t < WW / 2) {
        float d   = (float)(2 * t + 1);
        float ang = d * (1.0f / WW);
        ac[t] = -(1.0f / (WW / 2)) * (cospif(ang) / sinpif(ang));
    }
    __syncthreads();
    float sum = 0.f;
    int idx = t - 1; if (idx < 0) idx += WW;
    #pragma unroll 4
    for (int j = 0; j < WW / 2; j++) {
        sum += ac[j] * row[idx];
        idx -= 2; if (idx < 0) idx += WW;
    }
    g_cat[dbase + t] = sum;
}

// ---------------------------------------------------------------------------
// Per-(b,c) affine combining inorm1 + FiLM:
//   scale = rstd*n1w*(1+gamma);  shift = (n1b - mean*rstd*n1w)*(1+gamma) + beta
// ---------------------------------------------------------------------------
__global__ void make_scale_shift(const float* __restrict__ n1w, const float* __restrict__ n1b,
                                 const float* __restrict__ gamma, const float* __restrict__ beta) {
    int bc = blockIdx.x * blockDim.x + threadIdx.x;
    if (bc >= BB * CC) return;
    int c = bc & 255;
    float m = g_mean1[bc], r = g_rstd1[bc];
    float gpo = 1.0f + gamma[c];
    float w = n1w[c];
    g_scale[bc] = r * w * gpo;
    g_shift[bc] = (n1b[c] - m * r * w) * gpo + beta[c];
}

__global__ void apply_affine() {
    int i4 = blockIdx.x * blockDim.x + threadIdx.x;
    if (i4 >= (BB * CC * SS) / 4) return;
    int i = i4 * 4;
    int bc = i / SS;
    float sc = g_scale[bc], sh = g_shift[bc];
    float4 v = ((const float4*)g_t0)[i4];
    v.x = v.x * sc + sh; v.y = v.y * sc + sh;
    v.z = v.z * sc + sh; v.w = v.w * sc + sh;
    ((float4*)g_t1)[i4] = v;
}

// ---------------------------------------------------------------------------
// SGEMM: C[m,n] = sum_k A[m,k]*B[k,n] (+bias[m]) (+epilogue)
//   EPI 1: GELU(exact) ;  EPI 2: + residual[m,n]
// 128x128x16 tiles, 256 threads, 8x8 per thread. All dims assumed divisible.
// grid: (N/128, M/128, batch). B/C/resid have per-batch offsets.
// ---------------------------------------------------------------------------
template<int EPI>
__global__ __launch_bounds__(256)
void sgemm(const float* __restrict__ A, const float* __restrict__ Bmat,
           const float* __restrict__ bias, const float* __restrict__ resid,
           float* __restrict__ Cm, int M, int N, int K) {
    __shared__ float As[16][132];
    __shared__ float Bs[16][128];

    int tid = threadIdx.x;
    int tx = tid & 15, ty = tid >> 4;
    int m0 = blockIdx.y * 128;
    int n0 = blockIdx.x * 128;
    int bz = blockIdx.z;

    const float* Bp = Bmat + (size_t)bz * K * N;
    float*       Cp = Cm   + (size_t)bz * M * N;
    const float* Rp = (EPI == 2) ? (resid + (size_t)bz * M * N) : nullptr;

    float acc[8][8];
    #pragma unroll
    for (int i = 0; i < 8; i++)
        #pragma unroll
        for (int j = 0; j < 8; j++) acc[i][j] = 0.f;

    for (int k0 = 0; k0 < K; k0 += 16) {
        #pragma unroll
        for (int it = 0; it < 2; it++) {
            int idx = tid + it * 256;
            int ar  = idx >> 2;
            int akc = (idx & 3) * 4;
            float4 av = *(const float4*)(A + (size_t)(m0 + ar) * K + k0 + akc);
            As[akc + 0][ar] = av.x;
            As[akc + 1][ar] = av.y;
            As[akc + 2][ar] = av.z;
            As[akc + 3][ar] = av.w;
            int br  = idx >> 5;
            int bnc = (idx & 31) * 4;
            *(float4*)&Bs[br][bnc] =
                *(const float4*)(Bp + (size_t)(k0 + br) * N + n0 + bnc);
        }
        __syncthreads();
        #pragma unroll
        for (int kk = 0; kk < 16; kk++) {
            float a[8], b[8];
            #pragma unroll
            for (int i = 0; i < 8; i++) a[i] = As[kk][ty * 8 + i];
            #pragma unroll
            for (int j = 0; j < 8; j++) b[j] = Bs[kk][tx * 8 + j];
            #pragma unroll
            for (int i = 0; i < 8; i++)
                #pragma unroll
                for (int j = 0; j < 8; j++)
                    acc[i][j] += a[i] * b[j];
        }
        __syncthreads();
    }

    #pragma unroll
    for (int i = 0; i < 8; i++) {
        int m = m0 + ty * 8 + i;
        float bv = bias[m];
        #pragma unroll
        for (int j = 0; j < 8; j++) {
            int n = n0 + tx * 8 + j;
            float v = acc[i][j] + bv;
            if (EPI == 1) v = 0.5f * v * (1.0f + erff(v * 0.70710678118654752f));
            if (EPI == 2) v += Rp[(size_t)m * N + n];
            Cp[(size_t)m * N + n] = v;
        }
    }
}

// ---------------------------------------------------------------------------
// Launch
// ---------------------------------------------------------------------------
extern "C" void kernel_launch(void* const* d_in, const int* in_sizes, int n_in,
                              void* d_out, int out_size) {
    const float* x      = (const float*)d_in[0];
    const float* gamma  = (const float*)d_in[1];
    const float* beta   = (const float*)d_in[2];
    const float* n0w    = (const float*)d_in[3];
    const float* n0b    = (const float*)d_in[4];
    const float* n1w    = (const float*)d_in[5];
    const float* n1b    = (const float*)d_in[6];
    const float* wr     = (const float*)d_in[7];
    const float* wi     = (const float*)d_in[8];
    const float* innerw = (const float*)d_in[9];
    const float* innerb = (const float*)d_in[10];
    const float* w1     = (const float*)d_in[11];
    const float* b1     = (const float*)d_in[12];
    const float* w2     = (const float*)d_in[13];
    const float* b2     = (const float*)d_in[14];
    float* out = (float*)d_out;

    float *p_cat, *p_t0, *p_t1, *p_u, *p_wcat, *p_mean0, *p_rstd0, *p_mean1, *p_rstd1;
    cudaGetSymbolAddress((void**)&p_cat,  g_cat);
    cudaGetSymbolAddress((void**)&p_t0,   g_t0);
    cudaGetSymbolAddress((void**)&p_t1,   g_t1);
    cudaGetSymbolAddress((void**)&p_u,    g_u);
    cudaGetSymbolAddress((void**)&p_wcat, g_wcat);
    cudaGetSymbolAddress((void**)&p_mean0, g_mean0);
    cudaGetSymbolAddress((void**)&p_rstd0, g_rstd0);
    cudaGetSymbolAddress((void**)&p_mean1, g_mean1);
    cudaGetSymbolAddress((void**)&p_rstd1, g_rstd1);

    // 1. pack weights
    pack_weights<<<(CC * KCAT + 255) / 256, 256>>>(wr, wi, innerw);
    // 2. inorm0 stats
    inorm_stats<<<BB * CC, 256>>>(x, p_mean0, p_rstd0);
    // 3. h0 + x copy into cat
    prep_cat<<<(BB * CC * SS / 4 + 255) / 256, 256>>>(x, n0w, n0b);
    // 4. Hilbert rows (section0 -> section1)
    hilbert_rows<<<BB * CC * HH, WW>>>();
    // 5. fused spectral+inner GEMM + GELU  [256 x 768] x [768 x 28800]
    sgemm<1><<<dim3(SS / 128, CC / 128, BB), 256>>>(p_wcat, p_cat, innerb, nullptr,
                                                    p_t0, CC, SS, KCAT);
    // 6. inorm1 stats
    inorm_stats<<<BB * CC, 256>>>(p_t0, p_mean1, p_rstd1);
    // 7. fold norm1 + FiLM into per-(b,c) affine
    make_scale_shift<<<(BB * CC + 255) / 256, 256>>>(n1w, n1b, gamma, beta);
    apply_affine<<<(BB * CC * SS / 4 + 255) / 256, 256>>>();
    // 8. mlp1 + GELU  [512 x 256] x [256 x 28800]
    sgemm<1><<<dim3(SS / 128, HID / 128, BB), 256>>>(w1, p_t1, b1, nullptr,
                                                     p_u, HID, SS, CC);
    // 9. mlp2 + bias + residual  [256 x 512] x [512 x 28800]
    sgemm<2><<<dim3(SS / 128, CC / 128, BB), 256>>>(w2, p_u, b2, x,
                                                    out, CC, SS, HID);
}

// round 2
// speedup vs baseline: 1.4438x; 1.4438x over previous
#include <cuda_runtime.h>
#include <cuda_bf16.h>
#include <math.h>

// Problem constants
#define BB 2
#define CC 256
#define HH 120
#define WW 240
#define SS (HH*WW)          // 28800
#define HID 512
#define KCAT 768            // h0 | hilbert(h0) | x

// ---------------------------------------------------------------------------
// Static scratch (no dynamic allocation allowed)
// ---------------------------------------------------------------------------
__device__ float g_cat  [(size_t)BB*KCAT*SS];  // [B][768][S]: h0 | g | x
__device__ float g_t0   [(size_t)BB*CC*SS];    // post GEMM1+GELU
__device__ float g_t1   [(size_t)BB*CC*SS];    // post norm1+FiLM
__device__ float g_u    [(size_t)BB*HID*SS];   // post mlp1+GELU
__device__ float g_wcat [CC*KCAT];             // packed [256 x 768] weight
__device__ float g_mean0[BB*CC];
__device__ float g_rstd0[BB*CC];
__device__ float g_mean1[BB*CC];
__device__ float g_rstd1[BB*CC];
__device__ float g_scale[BB*CC];
__device__ float g_shift[BB*CC];

// ---------------------------------------------------------------------------
// Pack Wcat[o][k]:  k<256: w_spec_r[k,o] ; k<512: w_spec_i[k-256,o] ; else inner_w[o,k-512]
// ---------------------------------------------------------------------------
__global__ void pack_weights(const float* __restrict__ wr,
                             const float* __restrict__ wi,
                             const float* __restrict__ iw) {
    int idx = blockIdx.x * blockDim.x + threadIdx.x;
    if (idx >= CC * KCAT) return;
    int o = idx / KCAT;
    int k = idx % KCAT;
    float v;
    if (k < 256)        v = wr[k * CC + o];
    else if (k < 512)   v = wi[(k - 256) * CC + o];
    else                v = iw[o * CC + (k - 512)];
    g_wcat[idx] = v;
}

// ---------------------------------------------------------------------------
// InstanceNorm statistics: one block per (b,c), float4 loads
// ---------------------------------------------------------------------------
__global__ void inorm_stats(const float* __restrict__ x,
                            float* __restrict__ mean, float* __restrict__ rstd) {
    __shared__ float ssum[8];
    __shared__ float ssq[8];
    int bc = blockIdx.x;
    const float4* p = (const float4*)(x + (size_t)bc * SS);
    int t = threadIdx.x;
    float s = 0.f, q = 0.f;
    for (int i = t; i < SS / 4; i += 256) {
        float4 v = p[i];
        s += v.x + v.y + v.z + v.w;
        q += v.x * v.x + v.y * v.y + v.z * v.z + v.w * v.w;
    }
    // warp reduce
    #pragma unroll
    for (int off = 16; off > 0; off >>= 1) {
        s += __shfl_xor_sync(0xffffffffu, s, off);
        q += __shfl_xor_sync(0xffffffffu, q, off);
    }
    int w = t >> 5, l = t & 31;
    if (l == 0) { ssum[w] = s; ssq[w] = q; }
    __syncthreads();
    if (t == 0) {
        float S = 0.f, Q = 0.f;
        #pragma unroll
        for (int i = 0; i < 8; i++) { S += ssum[i]; Q += ssq[i]; }
        float m = S * (1.0f / SS);
        float var = Q * (1.0f / SS) - m * m;
        mean[bc] = m;
        rstd[bc] = rsqrtf(var + 1e-5f);
    }
}

// ---------------------------------------------------------------------------
// Write h0 = inorm0(x) into cat section 0, copy x into cat section 2 (float4)
// ---------------------------------------------------------------------------
__global__ void prep_cat(const float* __restrict__ x,
                         const float* __restrict__ n0w, const float* __restrict__ n0b) {
    int i4 = blockIdx.x * blockDim.x + threadIdx.x;       // 0 .. B*C*S/4
    if (i4 >= (BB * CC * SS) / 4) return;
    int i = i4 * 4;
    int bc = i / SS;
    int s  = i % SS;
    int b = bc >> 8;
    int c = bc & 255;
    float4 v = ((const float4*)x)[i4];
    float m = g_mean0[bc], r = g_rstd0[bc];
    float w = n0w[c], bb = n0b[c];
    float sc = r * w;
    float sh = -m * r * w + bb;
    float4 h;
    h.x = v.x * sc + sh; h.y = v.y * sc + sh;
    h.z = v.z * sc + sh; h.w = v.w * sc + sh;
    size_t base0 = ((size_t)b * KCAT + c)       * SS + s;
    size_t base2 = ((size_t)b * KCAT + 512 + c) * SS + s;
    *(float4*)&g_cat[base0] = h;
    *(float4*)&g_cat[base2] = v;
}

// ---------------------------------------------------------------------------
// Hilbert-like circular conv along W, parity-split form:
//   g[2u]   = sum_j ac[j] * odd [(u-1-j) mod 120]
//   g[2u+1] = sum_j ac[j] * even[(u-j)   mod 120]
// where even[v]=h0[2v], odd[v]=h0[2v+1], ac[j] = -(1/120)*cot(pi*(2j+1)/240).
// Parity arrays duplicated to length 240 -> no modulo in inner loop.
// 8 rows per block, 240 threads (8 x 30), 8 outputs/thread, rolling float4
// windows: per 4 taps = 3 x LDS.128 + 32 FFMA.
// ---------------------------------------------------------------------------
#define RPB 8
__global__ __launch_bounds__(240)
void hilbert_rows() {
    __shared__ __align__(16) float ev[RPB][240];  // even parity, duplicated
    __shared__ __align__(16) float od[RPB][240];  // odd parity, duplicated
    __shared__ __align__(16) float ac[120];

    int tid = threadIdx.x;                 // 0..239
    int r0  = blockIdx.x * RPB;            // global row index (b,c,h-major)
    int b   = r0 / (CC * HH);
    int rem = r0 % (CC * HH);
    int c   = rem / HH;
    int h0r = rem % HH;                    // 8 | 120, so block stays in one (b,c)

    size_t sbase = ((size_t)b * KCAT + c)        * SS + (size_t)h0r * WW;
    size_t dbase = ((size_t)b * KCAT + 256 + c)  * SS + (size_t)h0r * WW;

    if (tid < 120) {
        float ang = (float)(2 * tid + 1) * (1.0f / 240.0f);
        ac[tid] = -(1.0f / 120.0f) * (cospif(ang) / sinpif(ang));
    }

    // Load 8 rows x 240 floats = 480 float4s; split into parity arrays (dup).
    const float4* src = (const float4*)&g_cat[sbase];
    #pragma unroll
    for (int it = 0; it < 2; it++) {
        int i4 = tid + it * 240;           // 0..479
        int rl = i4 / 60;                  // local row
        int q  = i4 % 60;                  // float4 within row (w = 4q)
        float4 v = src[rl * 60 + q];
        float2 e2 = make_float2(v.x, v.z);
        float2 o2 = make_float2(v.y, v.w);
        *(float2*)&ev[rl][2 * q]       = e2;
        *(float2*)&ev[rl][2 * q + 120] = e2;
        *(float2*)&od[rl][2 * q]       = o2;
        *(float2*)&od[rl][2 * q + 120] = o2;
    }
    __syncthreads();

    int rl   = tid / 30;
    int lane = tid % 30;
    int u0   = 4 * lane;                   // thread outputs u = u0..u0+3 (both parities)
    const float* E = ev[rl];
    const float* O = od[rl];

    float aE[4] = {0.f, 0.f, 0.f, 0.f};    // even outputs g[2(u0+k)]
    float aO[4] = {0.f, 0.f, 0.f, 0.f};    // odd  outputs g[2(u0+k)+1]

    float4 curO = *(const float4*)&O[u0 + 120];
    float4 curE = *(const float4*)&E[u0 + 120];

    #pragma unroll
    for (int g = 0; g < 30; g++) {
        float4 a4   = *(const float4*)&ac[4 * g];
        float4 newO = *(const float4*)&O[u0 + 116 - 4 * g];
        float4 newE = *(const float4*)&E[u0 + 116 - 4 * g];
        float cO[8] = {newO.x, newO.y, newO.z, newO.w, curO.x, curO.y, curO.z, curO.w};
        float cE[8] = {newE.x, newE.y, newE.z, newE.w, curE.x, curE.y, curE.z, curE.w};
        float at[4] = {a4.x, a4.y, a4.z, a4.w};
        #pragma unroll
        for (int t = 0; t < 4; t++) {
            float a = at[t];
            #pragma unroll
            for (int k = 0; k < 4; k++) {
                aE[k] += a * cO[3 - t + k];   // g[2u]:   odd array, concat idx 3-t+k
                aO[k] += a * cE[4 - t + k];   // g[2u+1]: even array, concat idx 4-t+k
            }
        }
        curO = newO; curE = newE;
    }

    // Interleave back: w = 8*lane .. 8*lane+7
    float* dst = &g_cat[dbase + (size_t)rl * WW + 8 * lane];
    *(float4*)&dst[0] = make_float4(aE[0], aO[0], aE[1], aO[1]);
    *(float4*)&dst[4] = make_float4(aE[2], aO[2], aE[3], aO[3]);
}

// ---------------------------------------------------------------------------
// Per-(b,c) affine combining inorm1 + FiLM
// ---------------------------------------------------------------------------
__global__ void make_scale_shift(const float* __restrict__ n1w, const float* __restrict__ n1b,
                                 const float* __restrict__ gamma, const float* __restrict__ beta) {
    int bc = blockIdx.x * blockDim.x + threadIdx.x;
    if (bc >= BB * CC) return;
    int c = bc & 255;
    float m = g_mean1[bc], r = g_rstd1[bc];
    float gpo = 1.0f + gamma[c];
    float w = n1w[c];
    g_scale[bc] = r * w * gpo;
    g_shift[bc] = (n1b[c] - m * r * w) * gpo + beta[c];
}

__global__ void apply_affine() {
    int i4 = blockIdx.x * blockDim.x + threadIdx.x;
    if (i4 >= (BB * CC * SS) / 4) return;
    int i = i4 * 4;
    int bc = i / SS;
    float sc = g_scale[bc], sh = g_shift[bc];
    float4 v = ((const float4*)g_t0)[i4];
    v.x = v.x * sc + sh; v.y = v.y * sc + sh;
    v.z = v.z * sc + sh; v.w = v.w * sc + sh;
    ((float4*)g_t1)[i4] = v;
}

// ---------------------------------------------------------------------------
// SGEMM, double-buffered smem, cp.async for B, reg-staged A transpose.
// C[m,n] = sum_k A[m,k]*B[k,n] (+bias[m]) (+epilogue)
//   EPI 1: GELU(exact) ;  EPI 2: + residual[m,n]
// 128x128x16 tiles, 256 threads, 8x8 per thread. All dims divisible.
// ---------------------------------------------------------------------------
template<int EPI>
__global__ __launch_bounds__(256)
void sgemm(const float* __restrict__ A, const float* __restrict__ Bmat,
           const float* __restrict__ bias, const float* __restrict__ resid,
           float* __restrict__ Cm, int M, int N, int K) {
    __shared__ float As[2][16][132];
    __shared__ float Bs[2][16][128];

    int tid = threadIdx.x;
    int tx = tid & 15, ty = tid >> 4;
    int m0 = blockIdx.y * 128;
    int n0 = blockIdx.x * 128;
    int bz = blockIdx.z;

    const float* Bp = Bmat + (size_t)bz * K * N;
    float*       Cp = Cm   + (size_t)bz * M * N;
    const float* Rp = (EPI == 2) ? (resid + (size_t)bz * M * N) : nullptr;

    float acc[8][8];
    #pragma unroll
    for (int i = 0; i < 8; i++)
        #pragma unroll
        for (int j = 0; j < 8; j++) acc[i][j] = 0.f;

    float4 aReg[2];

    auto ldA = [&](int k0) {
        #pragma unroll
        for (int it = 0; it < 2; it++) {
            int idx = tid + it * 256;
            int ar  = idx >> 2;
            int akc = (idx & 3) * 4;
            aReg[it] = *(const float4*)(A + (size_t)(m0 + ar) * K + k0 + akc);
        }
    };
    auto stA = [&](int buf) {
        #pragma unroll
        for (int it = 0; it < 2; it++) {
            int idx = tid + it * 256;
            int ar  = idx >> 2;
            int akc = (idx & 3) * 4;
            As[buf][akc + 0][ar] = aReg[it].x;
            As[buf][akc + 1][ar] = aReg[it].y;
            As[buf][akc + 2][ar] = aReg[it].z;
            As[buf][akc + 3][ar] = aReg[it].w;
        }
    };
    auto cpB = [&](int k0, int buf) {
        #pragma unroll
        for (int it = 0; it < 2; it++) {
            int idx = tid + it * 256;
            int br  = idx >> 5;
            int bnc = (idx & 31) * 4;
            const float* gp = Bp + (size_t)(k0 + br) * N + n0 + bnc;
            unsigned dst = (unsigned)__cvta_generic_to_shared(&Bs[buf][br][bnc]);
            asm volatile("cp.async.cg.shared.global [%0], [%1], 16;\n" :: "r"(dst), "l"(gp));
        }
    };
    auto compute = [&](int buf) {
        #pragma unroll
        for (int kk = 0; kk < 16; kk++) {
            float a[8], b[8];
            *(float4*)&a[0] = *(const float4*)&As[buf][kk][ty * 8];
            *(float4*)&a[4] = *(const float4*)&As[buf][kk][ty * 8 + 4];
            *(float4*)&b[0] = *(const float4*)&Bs[buf][kk][tx * 8];
            *(float4*)&b[4] = *(const float4*)&Bs[buf][kk][tx * 8 + 4];
            #pragma unroll
            for (int i = 0; i < 8; i++)
                #pragma unroll
                for (int j = 0; j < 8; j++)
                    acc[i][j] += a[i] * b[j];
        }
    };

    // prologue
    ldA(0);
    cpB(0, 0);
    asm volatile("cp.async.commit_group;\n");
    stA(0);
    asm volatile("cp.async.wait_group 0;\n");
    __syncthreads();

    int buf = 0;
    for (int k0 = 16; k0 < K; k0 += 16) {
        ldA(k0);
        cpB(k0, buf ^ 1);
        asm volatile("cp.async.commit_group;\n");
        compute(buf);
        stA(buf ^ 1);
        asm volatile("cp.async.wait_group 0;\n");
        __syncthreads();
        buf ^= 1;
    }
    compute(buf);

    #pragma unroll
    for (int i = 0; i < 8; i++) {
        int m = m0 + ty * 8 + i;
        float bv = bias[m];
        #pragma unroll
        for (int j = 0; j < 8; j++) {
            int n = n0 + tx * 8 + j;
            float v = acc[i][j] + bv;
            if (EPI == 1) v = 0.5f * v * (1.0f + erff(v * 0.70710678118654752f));
            if (EPI == 2) v += Rp[(size_t)m * N + n];
            Cp[(size_t)m * N + n] = v;
        }
    }
}

// ---------------------------------------------------------------------------
// Launch
// ---------------------------------------------------------------------------
extern "C" void kernel_launch(void* const* d_in, const int* in_sizes, int n_in,
                              void* d_out, int out_size) {
    const float* x      = (const float*)d_in[0];
    const float* gamma  = (const float*)d_in[1];
    const float* beta   = (const float*)d_in[2];
    const float* n0w    = (const float*)d_in[3];
    const float* n0b    = (const float*)d_in[4];
    const float* n1w    = (const float*)d_in[5];
    const float* n1b    = (const float*)d_in[6];
    const float* wr     = (const float*)d_in[7];
    const float* wi     = (const float*)d_in[8];
    const float* innerw = (const float*)d_in[9];
    const float* innerb = (const float*)d_in[10];
    const float* w1     = (const float*)d_in[11];
    const float* b1     = (const float*)d_in[12];
    const float* w2     = (const float*)d_in[13];
    const float* b2     = (const float*)d_in[14];
    float* out = (float*)d_out;

    float *p_cat, *p_t0, *p_t1, *p_u, *p_wcat, *p_mean0, *p_rstd0, *p_mean1, *p_rstd1;
    cudaGetSymbolAddress((void**)&p_cat,  g_cat);
    cudaGetSymbolAddress((void**)&p_t0,   g_t0);
    cudaGetSymbolAddress((void**)&p_t1,   g_t1);
    cudaGetSymbolAddress((void**)&p_u,    g_u);
    cudaGetSymbolAddress((void**)&p_wcat, g_wcat);
    cudaGetSymbolAddress((void**)&p_mean0, g_mean0);
    cudaGetSymbolAddress((void**)&p_rstd0, g_rstd0);
    cudaGetSymbolAddress((void**)&p_mean1, g_mean1);
    cudaGetSymbolAddress((void**)&p_rstd1, g_rstd1);

    // 1. pack weights
    pack_weights<<<(CC * KCAT + 255) / 256, 256>>>(wr, wi, innerw);
    // 2. inorm0 stats
    inorm_stats<<<BB * CC, 256>>>(x, p_mean0, p_rstd0);
    // 3. h0 + x copy into cat
    prep_cat<<<(BB * CC * SS / 4 + 255) / 256, 256>>>(x, n0w, n0b);
    // 4. Hilbert rows (section0 -> section1), parity-split + rolling windows
    hilbert_rows<<<(BB * CC * HH) / RPB, 240>>>();
    // 5. fused spectral+inner GEMM + GELU  [256 x 768] x [768 x 28800]
    sgemm<1><<<dim3(SS / 128, CC / 128, BB), 256>>>(p_wcat, p_cat, innerb, nullptr,
                                                    p_t0, CC, SS, KCAT);
    // 6. inorm1 stats
    inorm_stats<<<BB * CC, 256>>>(p_t0, p_mean1, p_rstd1);
    // 7. fold norm1 + FiLM into per-(b,c) affine
    make_scale_shift<<<(BB * CC + 255) / 256, 256>>>(n1w, n1b, gamma, beta);
    apply_affine<<<(BB * CC * SS / 4 + 255) / 256, 256>>>();
    // 8. mlp1 + GELU  [512 x 256] x [256 x 28800]
    sgemm<1><<<dim3(SS / 128, HID / 128, BB), 256>>>(w1, p_t1, b1, nullptr,
                                                     p_u, HID, SS, CC);
    // 9. mlp2 + bias + residual  [256 x 512] x [512 x 28800]
    sgemm<2><<<dim3(SS / 128, CC / 128, BB), 256>>>(w2, p_u, b2, x,
                                                    out, CC, SS, HID);
}

// round 3
// speedup vs baseline: 1.7370x; 1.2031x over previous
#include <cuda_runtime.h>
#include <cuda_bf16.h>
#include <math.h>

// Problem constants
#define BB 2
#define CC 256
#define HH 120
#define WW 240
#define SS (HH*WW)          // 28800
#define HID 512
#define K1 512              // GEMM1 K: [x | hilbert(x)]

// ---------------------------------------------------------------------------
// Static scratch
// ---------------------------------------------------------------------------
__device__ float g_hx  [(size_t)BB*CC*SS];     // hilbert(x)
__device__ float g_t0  [(size_t)BB*CC*SS];     // post GEMM1+GELU
__device__ float g_u   [(size_t)BB*HID*SS];    // post mlp1+GELU
__device__ float g_at1 [BB*K1*CC];             // GEMM1 AT [b][k=512][m=256]
__device__ float g_at2 [BB*CC*HID];            // mlp1  AT [b][k=256][m=512]
__device__ float g_w2t [HID*CC];               // mlp2  AT [k=512][m=256]
__device__ float g_bias1[BB*CC];
__device__ float g_bias2[BB*HID];
__device__ float g_mean0[BB*CC];
__device__ float g_rstd0[BB*CC];
__device__ float g_mean1[BB*CC];
__device__ float g_rstd1[BB*CC];
__device__ float g_scale[BB*CC];
__device__ float g_shift[BB*CC];

// ---------------------------------------------------------------------------
// InstanceNorm statistics: one block per (b,c)
// ---------------------------------------------------------------------------
__global__ void inorm_stats(const float* __restrict__ x,
                            float* __restrict__ mean, float* __restrict__ rstd) {
    __shared__ float ssum[8];
    __shared__ float ssq[8];
    int bc = blockIdx.x;
    const float4* p = (const float4*)(x + (size_t)bc * SS);
    int t = threadIdx.x;
    float s = 0.f, q = 0.f;
    for (int i = t; i < SS / 4; i += 256) {
        float4 v = p[i];
        s += v.x + v.y + v.z + v.w;
        q += v.x * v.x + v.y * v.y + v.z * v.z + v.w * v.w;
    }
    #pragma unroll
    for (int off = 16; off > 0; off >>= 1) {
        s += __shfl_xor_sync(0xffffffffu, s, off);
        q += __shfl_xor_sync(0xffffffffu, q, off);
    }
    int w = t >> 5, l = t & 31;
    if (l == 0) { ssum[w] = s; ssq[w] = q; }
    __syncthreads();
    if (t == 0) {
        float S = 0.f, Q = 0.f;
        #pragma unroll
        for (int i = 0; i < 8; i++) { S += ssum[i]; Q += ssq[i]; }
        float m = S * (1.0f / SS);
        float var = Q * (1.0f / SS) - m * m;
        mean[bc] = m;
        rstd[bc] = rsqrtf(var + 1e-5f);
    }
}

// ---------------------------------------------------------------------------
// Hilbert-like circular conv along W on raw x (parity-split, rolling windows)
// ---------------------------------------------------------------------------
#define RPB 8
__global__ __launch_bounds__(240)
void hilbert_rows(const float* __restrict__ x) {
    __shared__ __align__(16) float ev[RPB][240];
    __shared__ __align__(16) float od[RPB][240];
    __shared__ __align__(16) float ac[120];

    int tid = threadIdx.x;
    int r0  = blockIdx.x * RPB;
    int bc  = r0 / HH;            // (b,c) combined, 8 | 120 keeps block in one bc
    int h0r = r0 % HH;

    size_t sbase = (size_t)bc * SS + (size_t)h0r * WW;

    if (tid < 120) {
        float ang = (float)(2 * tid + 1) * (1.0f / 240.0f);
        ac[tid] = -(1.0f / 120.0f) * (cospif(ang) / sinpif(ang));
    }

    const float4* src = (const float4*)&x[sbase];
    #pragma unroll
    for (int it = 0; it < 2; it++) {
        int i4 = tid + it * 240;
        int rl = i4 / 60;
        int q  = i4 % 60;
        float4 v = src[rl * 60 + q];
        float2 e2 = make_float2(v.x, v.z);
        float2 o2 = make_float2(v.y, v.w);
        *(float2*)&ev[rl][2 * q]       = e2;
        *(float2*)&ev[rl][2 * q + 120] = e2;
        *(float2*)&od[rl][2 * q]       = o2;
        *(float2*)&od[rl][2 * q + 120] = o2;
    }
    __syncthreads();

    int rl   = tid / 30;
    int lane = tid % 30;
    int u0   = 4 * lane;
    const float* E = ev[rl];
    const float* O = od[rl];

    float aE[4] = {0.f, 0.f, 0.f, 0.f};
    float aO[4] = {0.f, 0.f, 0.f, 0.f};

    float4 curO = *(const float4*)&O[u0 + 120];
    float4 curE = *(const float4*)&E[u0 + 120];

    #pragma unroll
    for (int g = 0; g < 30; g++) {
        float4 a4   = *(const float4*)&ac[4 * g];
        float4 newO = *(const float4*)&O[u0 + 116 - 4 * g];
        float4 newE = *(const float4*)&E[u0 + 116 - 4 * g];
        float cO[8] = {newO.x, newO.y, newO.z, newO.w, curO.x, curO.y, curO.z, curO.w};
        float cE[8] = {newE.x, newE.y, newE.z, newE.w, curE.x, curE.y, curE.z, curE.w};
        float at[4] = {a4.x, a4.y, a4.z, a4.w};
        #pragma unroll
        for (int t = 0; t < 4; t++) {
            float a = at[t];
            #pragma unroll
            for (int k = 0; k < 4; k++) {
                aE[k] += a * cO[3 - t + k];
                aO[k] += a * cE[4 - t + k];
            }
        }
        curO = newO; curE = newE;
    }

    float* dst = &g_hx[sbase + (size_t)rl * WW + 8 * lane];
    *(float4*)&dst[0] = make_float4(aE[0], aO[0], aE[1], aO[1]);
    *(float4*)&dst[4] = make_float4(aE[2], aO[2], aE[3], aO[3]);
}

// ---------------------------------------------------------------------------
// Fold 1: AT1[b][k][o]  (k<256: Wr[k,o]*sc0 + iw[o,k] ; else Wi[k-256,o]*sc0)
// ---------------------------------------------------------------------------
__global__ void fold1(const float* __restrict__ wr, const float* __restrict__ wi,
                      const float* __restrict__ iw, const float* __restrict__ n0w) {
    int idx = blockIdx.x * blockDim.x + threadIdx.x;
    if (idx >= BB * K1 * CC) return;
    int b = idx / (K1 * CC);
    int r = idx % (K1 * CC);
    int k = r / CC;
    int o = r % CC;
    int kk = (k < CC) ? k : k - CC;
    float sc = g_rstd0[b * CC + kk] * n0w[kk];
    float v;
    if (k < CC) v = wr[k * CC + o] * sc + iw[o * CC + k];
    else        v = wi[kk * CC + o] * sc;
    g_at1[idx] = v;
}

// bias1[b][o] = inner_b[o] + sum_k Wr[k,o]*sh0[b,k]
__global__ void fold1_bias(const float* __restrict__ wr, const float* __restrict__ ib,
                           const float* __restrict__ n0w, const float* __restrict__ n0b) {
    __shared__ float red[8];
    int o = blockIdx.x, b = blockIdx.y;
    int t = threadIdx.x;
    float m = g_mean0[b * CC + t], rs = g_rstd0[b * CC + t];
    float sh = n0b[t] - m * rs * n0w[t];
    float s = wr[t * CC + o] * sh;
    #pragma unroll
    for (int off = 16; off > 0; off >>= 1) s += __shfl_xor_sync(0xffffffffu, s, off);
    if ((t & 31) == 0) red[t >> 5] = s;
    __syncthreads();
    if (t == 0) {
        float S = 0.f;
        #pragma unroll
        for (int i = 0; i < 8; i++) S += red[i];
        g_bias1[b * CC + o] = ib[o] + S;
    }
}

// ---------------------------------------------------------------------------
// norm1 + FiLM -> per-(b,c) affine
// ---------------------------------------------------------------------------
__global__ void make_scale_shift(const float* __restrict__ n1w, const float* __restrict__ n1b,
                                 const float* __restrict__ gamma, const float* __restrict__ beta) {
    int bc = blockIdx.x * blockDim.x + threadIdx.x;
    if (bc >= BB * CC) return;
    int c = bc & 255;
    float m = g_mean1[bc], r = g_rstd1[bc];
    float gpo = 1.0f + gamma[c];
    float w = n1w[c];
    g_scale[bc] = r * w * gpo;
    g_shift[bc] = (n1b[c] - m * r * w) * gpo + beta[c];
}

// Fold 2: AT2[b][k][m] = w1[m,k]*scale[b,k]
__global__ void fold2(const float* __restrict__ w1) {
    int idx = blockIdx.x * blockDim.x + threadIdx.x;
    if (idx >= BB * CC * HID) return;
    int b = idx / (CC * HID);
    int r = idx % (CC * HID);
    int k = r / HID;
    int m = r % HID;
    g_at2[idx] = w1[m * CC + k] * g_scale[b * CC + k];
}

// bias2[b][m] = b1[m] + sum_k w1[m,k]*shift[b,k]
__global__ void fold2_bias(const float* __restrict__ w1, const float* __restrict__ b1) {
    __shared__ float red[8];
    int m = blockIdx.x, b = blockIdx.y;
    int t = threadIdx.x;
    float s = w1[m * CC + t] * g_shift[b * CC + t];
    #pragma unroll
    for (int off = 16; off > 0; off >>= 1) s += __shfl_xor_sync(0xffffffffu, s, off);
    if ((t & 31) == 0) red[t >> 5] = s;
    __syncthreads();
    if (t == 0) {
        float S = 0.f;
        #pragma unroll
        for (int i = 0; i < 8; i++) S += red[i];
        g_bias2[b * HID + m] = b1[m] + S;
    }
}

// w2t[k][m] = w2[m][k]
__global__ void pack_w2t(const float* __restrict__ w2) {
    int idx = blockIdx.x * blockDim.x + threadIdx.x;
    if (idx >= HID * CC) return;
    int k = idx / CC, m = idx % CC;
    g_w2t[idx] = w2[m * HID + k];
}

// ---------------------------------------------------------------------------
// SGEMM: C[m,n] = sum_k AT[k,m]*B[k,n] + bias[m], 3-stage cp.async ring.
// B rows come from B1 (k<Ksplit) or B2 (k>=Ksplit). EPI 1: GELU; EPI 2: +resid.
// 128x128x16 tiles, 256 threads, 8x8 per thread. All dims divisible by tiles.
// ---------------------------------------------------------------------------
template<int EPI>
__global__ __launch_bounds__(256)
void sgemm(const float* __restrict__ AT, long aStride,
           const float* __restrict__ B1, long b1Stride,
           const float* __restrict__ B2, long b2Stride, int Ksplit,
           const float* __restrict__ bias, int biasStride,
           const float* __restrict__ resid,
           float* __restrict__ C, int M, int N, int K) {
    __shared__ float As[3][16][128];
    __shared__ float Bs[3][16][128];

    int tid = threadIdx.x;
    int tx = tid & 15, ty = tid >> 4;
    int m0 = blockIdx.y * 128;
    int n0 = blockIdx.x * 128;
    int bz = blockIdx.z;

    const float* ATp = AT + (size_t)bz * aStride;
    float*       Cp  = C  + (size_t)bz * M * N;

    float acc[8][8];
    #pragma unroll
    for (int i = 0; i < 8; i++)
        #pragma unroll
        for (int j = 0; j < 8; j++) acc[i][j] = 0.f;

    auto cpTile = [&](int k0, int st) {
        #pragma unroll
        for (int it = 0; it < 2; it++) {
            int idx = tid + it * 256;
            int r  = idx >> 5;
            int c4 = (idx & 31) * 4;
            const float* ga = ATp + (size_t)(k0 + r) * M + m0 + c4;
            unsigned da = (unsigned)__cvta_generic_to_shared(&As[st][r][c4]);
            asm volatile("cp.async.cg.shared.global [%0], [%1], 16;\n" :: "r"(da), "l"(ga));
            int k = k0 + r;
            const float* gb = (k < Ksplit)
                ? B1 + (size_t)bz * b1Stride + (size_t)k * N + n0 + c4
                : B2 + (size_t)bz * b2Stride + (size_t)(k - Ksplit) * N + n0 + c4;
            unsigned db = (unsigned)__cvta_generic_to_shared(&Bs[st][r][c4]);
            asm volatile("cp.async.cg.shared.global [%0], [%1], 16;\n" :: "r"(db), "l"(gb));
        }
        asm volatile("cp.async.commit_group;\n");
    };
    auto compute = [&](int st) {
        #pragma unroll
        for (int kk = 0; kk < 16; kk++) {
            float a[8], b[8];
            *(float4*)&a[0] = *(const float4*)&As[st][kk][ty * 8];
            *(float4*)&a[4] = *(const float4*)&As[st][kk][ty * 8 + 4];
            *(float4*)&b[0] = *(const float4*)&Bs[st][kk][tx * 8];
            *(float4*)&b[4] = *(const float4*)&Bs[st][kk][tx * 8 + 4];
            #pragma unroll
            for (int i = 0; i < 8; i++)
                #pragma unroll
                for (int j = 0; j < 8; j++)
                    acc[i][j] += a[i] * b[j];
        }
    };

    int T = K >> 4;
    cpTile(0, 0);
    cpTile(16, 1);
    for (int t = 0; t < T - 2; t++) {
        asm volatile("cp.async.wait_group 1;\n");
        __syncthreads();
        compute(t % 3);
        cpTile((t + 2) * 16, (t + 2) % 3);
    }
    asm volatile("cp.async.wait_group 1;\n");
    __syncthreads();
    compute((T - 2) % 3);
    asm volatile("cp.async.wait_group 0;\n");
    __syncthreads();
    compute((T - 1) % 3);

    #pragma unroll
    for (int i = 0; i < 8; i++) {
        int m = m0 + ty * 8 + i;
        float bv = bias[bz * biasStride + m];
        #pragma unroll
        for (int j = 0; j < 8; j++) {
            int n = n0 + tx * 8 + j;
            float v = acc[i][j] + bv;
            if (EPI == 1) v = 0.5f * v * (1.0f + erff(v * 0.70710678118654752f));
            if (EPI == 2) v += resid[(size_t)bz * M * N + (size_t)m * N + n];
            Cp[(size_t)m * N + n] = v;
        }
    }
}

// ---------------------------------------------------------------------------
// Launch
// ---------------------------------------------------------------------------
extern "C" void kernel_launch(void* const* d_in, const int* in_sizes, int n_in,
                              void* d_out, int out_size) {
    const float* x      = (const float*)d_in[0];
    const float* gamma  = (const float*)d_in[1];
    const float* beta   = (const float*)d_in[2];
    const float* n0w    = (const float*)d_in[3];
    const float* n0b    = (const float*)d_in[4];
    const float* n1w    = (const float*)d_in[5];
    const float* n1b    = (const float*)d_in[6];
    const float* wr     = (const float*)d_in[7];
    const float* wi     = (const float*)d_in[8];
    const float* innerw = (const float*)d_in[9];
    const float* innerb = (const float*)d_in[10];
    const float* w1     = (const float*)d_in[11];
    const float* b1     = (const float*)d_in[12];
    const float* w2     = (const float*)d_in[13];
    const float* b2     = (const float*)d_in[14];
    float* out = (float*)d_out;

    float *p_hx, *p_t0, *p_u, *p_at1, *p_at2, *p_w2t, *p_b1f, *p_b2f;
    float *p_mean0, *p_rstd0, *p_mean1, *p_rstd1;
    cudaGetSymbolAddress((void**)&p_hx,  g_hx);
    cudaGetSymbolAddress((void**)&p_t0,  g_t0);
    cudaGetSymbolAddress((void**)&p_u,   g_u);
    cudaGetSymbolAddress((void**)&p_at1, g_at1);
    cudaGetSymbolAddress((void**)&p_at2, g_at2);
    cudaGetSymbolAddress((void**)&p_w2t, g_w2t);
    cudaGetSymbolAddress((void**)&p_b1f, g_bias1);
    cudaGetSymbolAddress((void**)&p_b2f, g_bias2);
    cudaGetSymbolAddress((void**)&p_mean0, g_mean0);
    cudaGetSymbolAddress((void**)&p_rstd0, g_rstd0);
    cudaGetSymbolAddress((void**)&p_mean1, g_mean1);
    cudaGetSymbolAddress((void**)&p_rstd1, g_rstd1);

    // weight prep
    pack_w2t<<<(HID * CC + 255) / 256, 256>>>(w2);
    // inorm0 stats
    inorm_stats<<<BB * CC, 256>>>(x, p_mean0, p_rstd0);
    // fold inorm0 into GEMM1 weights + bias
    fold1<<<(BB * K1 * CC + 255) / 256, 256>>>(wr, wi, innerw, n0w);
    fold1_bias<<<dim3(CC, BB), 256>>>(wr, innerb, n0w, n0b);
    // hilbert(x)
    hilbert_rows<<<(BB * CC * HH) / RPB, 240>>>(x);
    // GEMM1 + GELU: [256 x 512] x [x ; hx] -> t0
    sgemm<1><<<dim3(SS / 128, CC / 128, BB), 256>>>(
        p_at1, (long)K1 * CC, x, (long)CC * SS, p_hx, (long)CC * SS, CC,
        p_b1f, CC, nullptr, p_t0, CC, SS, K1);
    // inorm1 stats + affine fold into mlp1
    inorm_stats<<<BB * CC, 256>>>(p_t0, p_mean1, p_rstd1);
    make_scale_shift<<<(BB * CC + 255) / 256, 256>>>(n1w, n1b, gamma, beta);
    fold2<<<(BB * CC * HID + 255) / 256, 256>>>(w1);
    fold2_bias<<<dim3(HID, BB), 256>>>(w1, b1);
    // mlp1 + GELU: [512 x 256] x t0 -> u
    sgemm<1><<<dim3(SS / 128, HID / 128, BB), 256>>>(
        p_at2, (long)CC * HID, p_t0, (long)CC * SS, p_t0, (long)CC * SS, CC,
        p_b2f, HID, nullptr, p_u, HID, SS, CC);
    // mlp2 + bias + residual: [256 x 512] x u + x -> out
    sgemm<2><<<dim3(SS / 128, CC / 128, BB), 256>>>(
        p_w2t, 0L, p_u, (long)HID * SS, p_u, (long)HID * SS, HID,
        b2, 0, x, out, CC, SS, HID);
}

// round 4
// speedup vs baseline: 3.7994x; 2.1873x over previous
#include <cuda_runtime.h>
#include <cuda_bf16.h>
#include <math.h>
#include <stdint.h>

// Problem constants
#define BB 2
#define CC 256
#define HH 120
#define WW 240
#define SS (HH*WW)          // 28800
#define HID 512
#define K1 512              // GEMM1 K: [x | hilbert(x)]

// ---------------------------------------------------------------------------
// Static scratch
// ---------------------------------------------------------------------------
__device__ float g_xr  [(size_t)BB*CC*SS];     // tf32-rounded copy of x
__device__ float g_hx  [(size_t)BB*CC*SS];     // hilbert(x), tf32-rounded
__device__ float g_t0  [(size_t)BB*CC*SS];     // post GEMM1+GELU (rounded)
__device__ float g_u   [(size_t)BB*HID*SS];    // post mlp1+GELU (rounded)
__device__ float g_at1 [BB*K1*CC];             // GEMM1 AT [b][k=512][m=256]
__device__ float g_at2 [BB*CC*HID];            // mlp1  AT [b][k=256][m=512]
__device__ float g_w2t [HID*CC];               // mlp2  AT [k=512][m=256]
__device__ float g_bias1[BB*CC];
__device__ float g_bias2[BB*HID];
__device__ float g_mean0[BB*CC];
__device__ float g_rstd0[BB*CC];
__device__ float g_mean1[BB*CC];
__device__ float g_rstd1[BB*CC];
__device__ float g_scale[BB*CC];
__device__ float g_shift[BB*CC];

__device__ __forceinline__ float rna(float x) {
    float r;
    asm("cvt.rna.tf32.f32 %0, %1;" : "=f"(r) : "f"(x));
    return r;
}

// ---------------------------------------------------------------------------
// InstanceNorm statistics (one block per (b,c)); optionally emit rounded copy
// ---------------------------------------------------------------------------
template<int EMIT>
__global__ void inorm_stats(const float* __restrict__ x,
                            float* __restrict__ mean, float* __restrict__ rstd,
                            float* __restrict__ xr) {
    __shared__ float ssum[8];
    __shared__ float ssq[8];
    int bc = blockIdx.x;
    const float4* p = (const float4*)(x + (size_t)bc * SS);
    float4* pr = (float4*)(xr + (size_t)bc * SS);
    int t = threadIdx.x;
    float s = 0.f, q = 0.f;
    for (int i = t; i < SS / 4; i += 256) {
        float4 v = p[i];
        s += v.x + v.y + v.z + v.w;
        q += v.x * v.x + v.y * v.y + v.z * v.z + v.w * v.w;
        if (EMIT) {
            float4 r = make_float4(rna(v.x), rna(v.y), rna(v.z), rna(v.w));
            pr[i] = r;
        }
    }
    #pragma unroll
    for (int off = 16; off > 0; off >>= 1) {
        s += __shfl_xor_sync(0xffffffffu, s, off);
        q += __shfl_xor_sync(0xffffffffu, q, off);
    }
    int w = t >> 5, l = t & 31;
    if (l == 0) { ssum[w] = s; ssq[w] = q; }
    __syncthreads();
    if (t == 0) {
        float S = 0.f, Q = 0.f;
        #pragma unroll
        for (int i = 0; i < 8; i++) { S += ssum[i]; Q += ssq[i]; }
        float m = S * (1.0f / SS);
        float var = Q * (1.0f / SS) - m * m;
        mean[bc] = m;
        rstd[bc] = rsqrtf(var + 1e-5f);
    }
}

// ---------------------------------------------------------------------------
// Hilbert circular conv along W (parity-split, rolling windows); rounded out
// ---------------------------------------------------------------------------
#define RPB 8
__global__ __launch_bounds__(240)
void hilbert_rows(const float* __restrict__ x) {
    __shared__ __align__(16) float ev[RPB][240];
    __shared__ __align__(16) float od[RPB][240];
    __shared__ __align__(16) float ac[120];

    int tid = threadIdx.x;
    int r0  = blockIdx.x * RPB;
    int bc  = r0 / HH;
    int h0r = r0 % HH;

    size_t sbase = (size_t)bc * SS + (size_t)h0r * WW;

    if (tid < 120) {
        float ang = (float)(2 * tid + 1) * (1.0f / 240.0f);
        ac[tid] = -(1.0f / 120.0f) * (cospif(ang) / sinpif(ang));
    }

    const float4* src = (const float4*)&x[sbase];
    #pragma unroll
    for (int it = 0; it < 2; it++) {
        int i4 = tid + it * 240;
        int rl = i4 / 60;
        int q  = i4 % 60;
        float4 v = src[rl * 60 + q];
        float2 e2 = make_float2(v.x, v.z);
        float2 o2 = make_float2(v.y, v.w);
        *(float2*)&ev[rl][2 * q]       = e2;
        *(float2*)&ev[rl][2 * q + 120] = e2;
        *(float2*)&od[rl][2 * q]       = o2;
        *(float2*)&od[rl][2 * q + 120] = o2;
    }
    __syncthreads();

    int rl   = tid / 30;
    int lane = tid % 30;
    int u0   = 4 * lane;
    const float* E = ev[rl];
    const float* O = od[rl];

    float aE[4] = {0.f, 0.f, 0.f, 0.f};
    float aO[4] = {0.f, 0.f, 0.f, 0.f};

    float4 curO = *(const float4*)&O[u0 + 120];
    float4 curE = *(const float4*)&E[u0 + 120];

    #pragma unroll
    for (int g = 0; g < 30; g++) {
        float4 a4   = *(const float4*)&ac[4 * g];
        float4 newO = *(const float4*)&O[u0 + 116 - 4 * g];
        float4 newE = *(const float4*)&E[u0 + 116 - 4 * g];
        float cO[8] = {newO.x, newO.y, newO.z, newO.w, curO.x, curO.y, curO.z, curO.w};
        float cE[8] = {newE.x, newE.y, newE.z, newE.w, curE.x, curE.y, curE.z, curE.w};
        float at[4] = {a4.x, a4.y, a4.z, a4.w};
        #pragma unroll
        for (int t = 0; t < 4; t++) {
            float a = at[t];
            #pragma unroll
            for (int k = 0; k < 4; k++) {
                aE[k] += a * cO[3 - t + k];
                aO[k] += a * cE[4 - t + k];
            }
        }
        curO = newO; curE = newE;
    }

    float* dst = &g_hx[sbase + (size_t)rl * WW + 8 * lane];
    *(float4*)&dst[0] = make_float4(rna(aE[0]), rna(aO[0]), rna(aE[1]), rna(aO[1]));
    *(float4*)&dst[4] = make_float4(rna(aE[2]), rna(aO[2]), rna(aE[3]), rna(aO[3]));
}

// ---------------------------------------------------------------------------
// Fold 1: AT1[b][k][o]  (k<256: Wr[k,o]*sc0 + iw[o,k] ; else Wi[k-256,o]*sc0)
// ---------------------------------------------------------------------------
__global__ void fold1(const float* __restrict__ wr, const float* __restrict__ wi,
                      const float* __restrict__ iw, const float* __restrict__ n0w) {
    int idx = blockIdx.x * blockDim.x + threadIdx.x;
    if (idx >= BB * K1 * CC) return;
    int b = idx / (K1 * CC);
    int r = idx % (K1 * CC);
    int k = r / CC;
    int o = r % CC;
    int kk = (k < CC) ? k : k - CC;
    float sc = g_rstd0[b * CC + kk] * n0w[kk];
    float v;
    if (k < CC) v = wr[k * CC + o] * sc + iw[o * CC + k];
    else        v = wi[kk * CC + o] * sc;
    g_at1[idx] = rna(v);
}

// bias1[b][o] = inner_b[o] + sum_k Wr[k,o]*sh0[b,k]
__global__ void fold1_bias(const float* __restrict__ wr, const float* __restrict__ ib,
                           const float* __restrict__ n0w, const float* __restrict__ n0b) {
    __shared__ float red[8];
    int o = blockIdx.x, b = blockIdx.y;
    int t = threadIdx.x;
    float m = g_mean0[b * CC + t], rs = g_rstd0[b * CC + t];
    float sh = n0b[t] - m * rs * n0w[t];
    float s = wr[t * CC + o] * sh;
    #pragma unroll
    for (int off = 16; off > 0; off >>= 1) s += __shfl_xor_sync(0xffffffffu, s, off);
    if ((t & 31) == 0) red[t >> 5] = s;
    __syncthreads();
    if (t == 0) {
        float S = 0.f;
        #pragma unroll
        for (int i = 0; i < 8; i++) S += red[i];
        g_bias1[b * CC + o] = ib[o] + S;
    }
}

// ---------------------------------------------------------------------------
// norm1 + FiLM -> per-(b,c) affine
// ---------------------------------------------------------------------------
__global__ void make_scale_shift(const float* __restrict__ n1w, const float* __restrict__ n1b,
                                 const float* __restrict__ gamma, const float* __restrict__ beta) {
    int bc = blockIdx.x * blockDim.x + threadIdx.x;
    if (bc >= BB * CC) return;
    int c = bc & 255;
    float m = g_mean1[bc], r = g_rstd1[bc];
    float gpo = 1.0f + gamma[c];
    float w = n1w[c];
    g_scale[bc] = r * w * gpo;
    g_shift[bc] = (n1b[c] - m * r * w) * gpo + beta[c];
}

// Fold 2: AT2[b][k][m] = w1[m,k]*scale[b,k]
__global__ void fold2(const float* __restrict__ w1) {
    int idx = blockIdx.x * blockDim.x + threadIdx.x;
    if (idx >= BB * CC * HID) return;
    int b = idx / (CC * HID);
    int r = idx % (CC * HID);
    int k = r / HID;
    int m = r % HID;
    g_at2[idx] = rna(w1[m * CC + k] * g_scale[b * CC + k]);
}

// bias2[b][m] = b1[m] + sum_k w1[m,k]*shift[b,k]
__global__ void fold2_bias(const float* __restrict__ w1, const float* __restrict__ b1) {
    __shared__ float red[8];
    int m = blockIdx.x, b = blockIdx.y;
    int t = threadIdx.x;
    float s = w1[m * CC + t] * g_shift[b * CC + t];
    #pragma unroll
    for (int off = 16; off > 0; off >>= 1) s += __shfl_xor_sync(0xffffffffu, s, off);
    if ((t & 31) == 0) red[t >> 5] = s;
    __syncthreads();
    if (t == 0) {
        float S = 0.f;
        #pragma unroll
        for (int i = 0; i < 8; i++) S += red[i];
        g_bias2[b * HID + m] = b1[m] + S;
    }
}

// w2t[k][m] = w2[m][k] (rounded)
__global__ void pack_w2t(const float* __restrict__ w2) {
    int idx = blockIdx.x * blockDim.x + threadIdx.x;
    if (idx >= HID * CC) return;
    int k = idx / CC, m = idx % CC;
    g_w2t[idx] = rna(w2[m * HID + k]);
}

// ---------------------------------------------------------------------------
// Tensor-core GEMM (mma.sync m16n8k8 tf32): C[m,n] = sum_k AT[k,m]*B[k,n]+bias
// 128x128x16 block tile, 8 warps (2x4), warp tile 64x32 = 4x4 mma frags.
// 3-stage cp.async ring. B rows from B1 (k<Ksplit) else B2.
// EPI 1: GELU ; EPI 2: +resid.  RND: round output to tf32 grid.
// ---------------------------------------------------------------------------
__device__ __forceinline__ void mma_tf32(float4& d,
    uint32_t a0, uint32_t a1, uint32_t a2, uint32_t a3,
    uint32_t b0, uint32_t b1) {
    asm volatile(
        "mma.sync.aligned.m16n8k8.row.col.f32.tf32.tf32.f32 "
        "{%0,%1,%2,%3}, {%4,%5,%6,%7}, {%8,%9}, {%0,%1,%2,%3};\n"
        : "+f"(d.x), "+f"(d.y), "+f"(d.z), "+f"(d.w)
        : "r"(a0), "r"(a1), "r"(a2), "r"(a3), "r"(b0), "r"(b1));
}

template<int EPI, int RND>
__global__ __launch_bounds__(256)
void mgemm(const float* __restrict__ AT, long aStride,
           const float* __restrict__ B1, long b1Stride,
           const float* __restrict__ B2, long b2Stride, int Ksplit,
           const float* __restrict__ bias, int biasStride,
           const float* __restrict__ resid,
           float* __restrict__ C, int M, int N, int K) {
    __shared__ float As[3][16][136];
    __shared__ float Bs[3][16][136];

    int tid  = threadIdx.x;
    int lane = tid & 31;
    int g    = lane >> 2;          // 0..7
    int tg   = lane & 3;           // 0..3
    int wid  = tid >> 5;
    int wm   = wid >> 2;           // 0..1
    int wn   = wid & 3;            // 0..3
    int mBase = wm * 64;
    int nBase = wn * 32;

    int m0 = blockIdx.y * 128;
    int n0 = blockIdx.x * 128;
    int bz = blockIdx.z;

    const float* ATp = AT + (size_t)bz * aStride;
    float*       Cp  = C  + (size_t)bz * M * N;

    float4 acc[4][4];
    #pragma unroll
    for (int i = 0; i < 4; i++)
        #pragma unroll
        for (int j = 0; j < 4; j++) acc[i][j] = make_float4(0.f, 0.f, 0.f, 0.f);

    auto cpTile = [&](int k0, int st) {
        #pragma unroll
        for (int it = 0; it < 2; it++) {
            int idx = tid + it * 256;
            int r  = idx >> 5;
            int c4 = (idx & 31) * 4;
            const float* ga = ATp + (size_t)(k0 + r) * M + m0 + c4;
            unsigned da = (unsigned)__cvta_generic_to_shared(&As[st][r][c4]);
            asm volatile("cp.async.cg.shared.global [%0], [%1], 16;\n" :: "r"(da), "l"(ga));
            int k = k0 + r;
            const float* gb = (k < Ksplit)
                ? B1 + (size_t)bz * b1Stride + (size_t)k * N + n0 + c4
                : B2 + (size_t)bz * b2Stride + (size_t)(k - Ksplit) * N + n0 + c4;
            unsigned db = (unsigned)__cvta_generic_to_shared(&Bs[st][r][c4]);
            asm volatile("cp.async.cg.shared.global [%0], [%1], 16;\n" :: "r"(db), "l"(gb));
        }
        asm volatile("cp.async.commit_group;\n");
    };

    auto compute = [&](int st) {
        const uint32_t* Au = (const uint32_t*)&As[st][0][0];
        const uint32_t* Bu = (const uint32_t*)&Bs[st][0][0];
        #pragma unroll
        for (int kk = 0; kk < 16; kk += 8) {
            uint32_t a[4][4], b[4][2];
            int ra = (kk + tg) * 136;
            int rb = (kk + tg + 4) * 136;
            #pragma unroll
            for (int i = 0; i < 4; i++) {
                int m = mBase + i * 16 + g;
                a[i][0] = Au[ra + m];
                a[i][1] = Au[ra + m + 8];
                a[i][2] = Au[rb + m];
                a[i][3] = Au[rb + m + 8];
            }
            #pragma unroll
            for (int j = 0; j < 4; j++) {
                int n = nBase + j * 8 + g;
                b[j][0] = Bu[ra + n];
                b[j][1] = Bu[rb + n];
            }
            #pragma unroll
            for (int i = 0; i < 4; i++)
                #pragma unroll
                for (int j = 0; j < 4; j++)
                    mma_tf32(acc[i][j], a[i][0], a[i][1], a[i][2], a[i][3],
                             b[j][0], b[j][1]);
        }
    };

    int T = K >> 4;
    cpTile(0, 0);
    cpTile(16, 1);
    for (int t = 0; t < T - 2; t++) {
        asm volatile("cp.async.wait_group 1;\n");
        __syncthreads();
        compute(t % 3);
        cpTile((t + 2) * 16, (t + 2) % 3);
    }
    asm volatile("cp.async.wait_group 1;\n");
    __syncthreads();
    compute((T - 2) % 3);
    asm volatile("cp.async.wait_group 0;\n");
    __syncthreads();
    compute((T - 1) % 3);

    // Epilogue
    #pragma unroll
    for (int i = 0; i < 4; i++) {
        int mr0 = m0 + mBase + i * 16 + g;
        int mr1 = mr0 + 8;
        float bv0 = bias[bz * biasStride + mr0];
        float bv1 = bias[bz * biasStride + mr1];
        #pragma unroll
        for (int j = 0; j < 4; j++) {
            int n = n0 + nBase + j * 8 + 2 * tg;
            float4 c = acc[i][j];
            float v0 = c.x + bv0, v1 = c.y + bv0;
            float v2 = c.z + bv1, v3 = c.w + bv1;
            if (EPI == 1) {
                v0 = 0.5f * v0 * (1.0f + erff(v0 * 0.70710678118654752f));
                v1 = 0.5f * v1 * (1.0f + erff(v1 * 0.70710678118654752f));
                v2 = 0.5f * v2 * (1.0f + erff(v2 * 0.70710678118654752f));
                v3 = 0.5f * v3 * (1.0f + erff(v3 * 0.70710678118654752f));
            }
            if (EPI == 2) {
                const float* rp = resid + (size_t)bz * M * N;
                float2 r0 = *(const float2*)&rp[(size_t)mr0 * N + n];
                float2 r1 = *(const float2*)&rp[(size_t)mr1 * N + n];
                v0 += r0.x; v1 += r0.y; v2 += r1.x; v3 += r1.y;
            }
            if (RND) { v0 = rna(v0); v1 = rna(v1); v2 = rna(v2); v3 = rna(v3); }
            *(float2*)&Cp[(size_t)mr0 * N + n] = make_float2(v0, v1);
            *(float2*)&Cp[(size_t)mr1 * N + n] = make_float2(v2, v3);
        }
    }
}

// ---------------------------------------------------------------------------
// Launch
// ---------------------------------------------------------------------------
extern "C" void kernel_launch(void* const* d_in, const int* in_sizes, int n_in,
                              void* d_out, int out_size) {
    const float* x      = (const float*)d_in[0];
    const float* gamma  = (const float*)d_in[1];
    const float* beta   = (const float*)d_in[2];
    const float* n0w    = (const float*)d_in[3];
    const float* n0b    = (const float*)d_in[4];
    const float* n1w    = (const float*)d_in[5];
    const float* n1b    = (const float*)d_in[6];
    const float* wr     = (const float*)d_in[7];
    const float* wi     = (const float*)d_in[8];
    const float* innerw = (const float*)d_in[9];
    const float* innerb = (const float*)d_in[10];
    const float* w1     = (const float*)d_in[11];
    const float* b1     = (const float*)d_in[12];
    const float* w2     = (const float*)d_in[13];
    const float* b2     = (const float*)d_in[14];
    float* out = (float*)d_out;

    float *p_xr, *p_hx, *p_t0, *p_u, *p_at1, *p_at2, *p_w2t, *p_b1f, *p_b2f;
    float *p_mean0, *p_rstd0, *p_mean1, *p_rstd1;
    cudaGetSymbolAddress((void**)&p_xr,  g_xr);
    cudaGetSymbolAddress((void**)&p_hx,  g_hx);
    cudaGetSymbolAddress((void**)&p_t0,  g_t0);
    cudaGetSymbolAddress((void**)&p_u,   g_u);
    cudaGetSymbolAddress((void**)&p_at1, g_at1);
    cudaGetSymbolAddress((void**)&p_at2, g_at2);
    cudaGetSymbolAddress((void**)&p_w2t, g_w2t);
    cudaGetSymbolAddress((void**)&p_b1f, g_bias1);
    cudaGetSymbolAddress((void**)&p_b2f, g_bias2);
    cudaGetSymbolAddress((void**)&p_mean0, g_mean0);
    cudaGetSymbolAddress((void**)&p_rstd0, g_rstd0);
    cudaGetSymbolAddress((void**)&p_mean1, g_mean1);
    cudaGetSymbolAddress((void**)&p_rstd1, g_rstd1);

    // weight prep
    pack_w2t<<<(HID * CC + 255) / 256, 256>>>(w2);
    // inorm0 stats + rounded copy of x
    inorm_stats<1><<<BB * CC, 256>>>(x, p_mean0, p_rstd0, p_xr);
    // fold inorm0 into GEMM1 weights + bias
    fold1<<<(BB * K1 * CC + 255) / 256, 256>>>(wr, wi, innerw, n0w);
    fold1_bias<<<dim3(CC, BB), 256>>>(wr, innerb, n0w, n0b);
    // hilbert(x)
    hilbert_rows<<<(BB * CC * HH) / RPB, 240>>>(x);
    // GEMM1 + GELU: [256 x 512] x [xr ; hx] -> t0 (rounded)
    mgemm<1, 1><<<dim3(SS / 128, CC / 128, BB), 256>>>(
        p_at1, (long)K1 * CC, p_xr, (long)CC * SS, p_hx, (long)CC * SS, CC,
        p_b1f, CC, nullptr, p_t0, CC, SS, K1);
    // inorm1 stats + affine fold into mlp1
    inorm_stats<0><<<BB * CC, 256>>>(p_t0, p_mean1, p_rstd1, nullptr);
    make_scale_shift<<<(BB * CC + 255) / 256, 256>>>(n1w, n1b, gamma, beta);
    fold2<<<(BB * CC * HID + 255) / 256, 256>>>(w1);
    fold2_bias<<<dim3(HID, BB), 256>>>(w1, b1);
    // mlp1 + GELU: [512 x 256] x t0 -> u (rounded)
    mgemm<1, 1><<<dim3(SS / 128, HID / 128, BB), 256>>>(
        p_at2, (long)CC * HID, p_t0, (long)CC * SS, p_t0, (long)CC * SS, CC,
        p_b2f, HID, nullptr, p_u, HID, SS, CC);
    // mlp2 + bias + residual: [256 x 512] x u + x -> out
    mgemm<2, 0><<<dim3(SS / 128, CC / 128, BB), 256>>>(
        p_w2t, 0L, p_u, (long)HID * SS, p_u, (long)HID * SS, HID,
        b2, 0, x, out, CC, SS, HID);
}

// round 6
// speedup vs baseline: 5.6973x; 1.4995x over previous
#include <cuda_runtime.h>
#include <cuda_bf16.h>
#include <math.h>
#include <stdint.h>

// Problem constants
#define BB 2
#define CC 256
#define HH 120
#define WW 240
#define SS (HH*WW)          // 28800
#define HID 512
#define K1 512              // GEMM1 K: [x | hilbert(x)]

typedef __nv_bfloat16 bf16;

// ---------------------------------------------------------------------------
// Static scratch
// ---------------------------------------------------------------------------
__device__ bf16  g_xr  [(size_t)BB*CC*SS];     // bf16 copy of x
__device__ bf16  g_hx  [(size_t)BB*CC*SS];     // hilbert(x), bf16
__device__ bf16  g_t0  [(size_t)BB*CC*SS];     // post GEMM1+GELU
__device__ bf16  g_u   [(size_t)BB*HID*SS];    // post mlp1+GELU
__device__ bf16  g_at1 [BB*K1*CC];             // GEMM1 AT [b][k=512][m=256]
__device__ bf16  g_at2 [BB*CC*HID];            // mlp1  AT [b][k=256][m=512]
__device__ bf16  g_w2t [HID*CC];               // mlp2  AT [k=512][m=256]
__device__ float g_bias1[BB*CC];
__device__ float g_bias2[BB*HID];
__device__ float g_mean0[BB*CC];
__device__ float g_rstd0[BB*CC];
__device__ float g_mean1[BB*CC];
__device__ float g_rstd1[BB*CC];

// ---------------------------------------------------------------------------
// InstanceNorm statistics (one block per (b,c)) over fp32 input; emit bf16 copy
// ---------------------------------------------------------------------------
__global__ void inorm_stats_f32(const float* __restrict__ x,
                                float* __restrict__ mean, float* __restrict__ rstd,
                                bf16* __restrict__ xr) {
    __shared__ float ssum[8];
    __shared__ float ssq[8];
    int bc = blockIdx.x;
    const float4* p = (const float4*)(x + (size_t)bc * SS);
    __nv_bfloat162* pr = (__nv_bfloat162*)(xr + (size_t)bc * SS);
    int t = threadIdx.x;
    float s = 0.f, q = 0.f;
    for (int i = t; i < SS / 4; i += 256) {
        float4 v = p[i];
        s += v.x + v.y + v.z + v.w;
        q += v.x * v.x + v.y * v.y + v.z * v.z + v.w * v.w;
        pr[2 * i]     = __floats2bfloat162_rn(v.x, v.y);
        pr[2 * i + 1] = __floats2bfloat162_rn(v.z, v.w);
    }
    #pragma unroll
    for (int off = 16; off > 0; off >>= 1) {
        s += __shfl_xor_sync(0xffffffffu, s, off);
        q += __shfl_xor_sync(0xffffffffu, q, off);
    }
    int w = t >> 5, l = t & 31;
    if (l == 0) { ssum[w] = s; ssq[w] = q; }
    __syncthreads();
    if (t == 0) {
        float S = 0.f, Q = 0.f;
        #pragma unroll
        for (int i = 0; i < 8; i++) { S += ssum[i]; Q += ssq[i]; }
        float m = S * (1.0f / SS);
        float var = Q * (1.0f / SS) - m * m;
        mean[bc] = m;
        rstd[bc] = rsqrtf(var + 1e-5f);
    }
}

// Same but over bf16 input (t0), no emit
__global__ void inorm_stats_bf16(const bf16* __restrict__ x,
                                 float* __restrict__ mean, float* __restrict__ rstd) {
    __shared__ float ssum[8];
    __shared__ float ssq[8];
    int bc = blockIdx.x;
    const uint4* p = (const uint4*)(x + (size_t)bc * SS);
    int t = threadIdx.x;
    float s = 0.f, q = 0.f;
    for (int i = t; i < SS / 8; i += 256) {
        uint4 u = p[i];
        const __nv_bfloat162* h = (const __nv_bfloat162*)&u;
        #pragma unroll
        for (int j = 0; j < 4; j++) {
            float2 f = __bfloat1622float2(h[j]);
            s += f.x + f.y;
            q += f.x * f.x + f.y * f.y;
        }
    }
    #pragma unroll
    for (int off = 16; off > 0; off >>= 1) {
        s += __shfl_xor_sync(0xffffffffu, s, off);
        q += __shfl_xor_sync(0xffffffffu, q, off);
    }
    int w = t >> 5, l = t & 31;
    if (l == 0) { ssum[w] = s; ssq[w] = q; }
    __syncthreads();
    if (t == 0) {
        float S = 0.f, Q = 0.f;
        #pragma unroll
        for (int i = 0; i < 8; i++) { S += ssum[i]; Q += ssq[i]; }
        float m = S * (1.0f / SS);
        float var = Q * (1.0f / SS) - m * m;
        mean[bc] = m;
        rstd[bc] = rsqrtf(var + 1e-5f);
    }
}

// ---------------------------------------------------------------------------
// Hilbert circular conv along W (parity-split, rolling windows); bf16 out
// ---------------------------------------------------------------------------
#define RPB 8
__global__ __launch_bounds__(240)
void hilbert_rows(const float* __restrict__ x) {
    __shared__ __align__(16) float ev[RPB][240];
    __shared__ __align__(16) float od[RPB][240];
    __shared__ __align__(16) float ac[120];

    int tid = threadIdx.x;
    int r0  = blockIdx.x * RPB;
    int bc  = r0 / HH;
    int h0r = r0 % HH;

    size_t sbase = (size_t)bc * SS + (size_t)h0r * WW;

    if (tid < 120) {
        float ang = (float)(2 * tid + 1) * (1.0f / 240.0f);
        ac[tid] = -(1.0f / 120.0f) * (cospif(ang) / sinpif(ang));
    }

    const float4* src = (const float4*)&x[sbase];
    #pragma unroll
    for (int it = 0; it < 2; it++) {
        int i4 = tid + it * 240;
        int rl = i4 / 60;
        int q  = i4 % 60;
        float4 v = src[rl * 60 + q];
        float2 e2 = make_float2(v.x, v.z);
        float2 o2 = make_float2(v.y, v.w);
        *(float2*)&ev[rl][2 * q]       = e2;
        *(float2*)&ev[rl][2 * q + 120] = e2;
        *(float2*)&od[rl][2 * q]       = o2;
        *(float2*)&od[rl][2 * q + 120] = o2;
    }
    __syncthreads();

    int rl   = tid / 30;
    int lane = tid % 30;
    int u0   = 4 * lane;
    const float* E = ev[rl];
    const float* O = od[rl];

    float aE[4] = {0.f, 0.f, 0.f, 0.f};
    float aO[4] = {0.f, 0.f, 0.f, 0.f};

    float4 curO = *(const float4*)&O[u0 + 120];
    float4 curE = *(const float4*)&E[u0 + 120];

    #pragma unroll
    for (int g = 0; g < 30; g++) {
        float4 a4   = *(const float4*)&ac[4 * g];
        float4 newO = *(const float4*)&O[u0 + 116 - 4 * g];
        float4 newE = *(const float4*)&E[u0 + 116 - 4 * g];
        float cO[8] = {newO.x, newO.y, newO.z, newO.w, curO.x, curO.y, curO.z, curO.w};
        float cE[8] = {newE.x, newE.y, newE.z, newE.w, curE.x, curE.y, curE.z, curE.w};
        float at[4] = {a4.x, a4.y, a4.z, a4.w};
        #pragma unroll
        for (int t = 0; t < 4; t++) {
            float a = at[t];
            #pragma unroll
            for (int k = 0; k < 4; k++) {
                aE[k] += a * cO[3 - t + k];
                aO[k] += a * cE[4 - t + k];
            }
        }
        curO = newO; curE = newE;
    }

    // Interleave back: w = 8*lane..+7, bf16
    uint4 pk;
    __nv_bfloat162* ph = (__nv_bfloat162*)&pk;
    ph[0] = __floats2bfloat162_rn(aE[0], aO[0]);
    ph[1] = __floats2bfloat162_rn(aE[1], aO[1]);
    ph[2] = __floats2bfloat162_rn(aE[2], aO[2]);
    ph[3] = __floats2bfloat162_rn(aE[3], aO[3]);
    *(uint4*)&g_hx[sbase + (size_t)rl * WW + 8 * lane] = pk;
}

// ---------------------------------------------------------------------------
// Fold 1: AT1[b][k][o]  (k<256: Wr[k,o]*sc0 + iw[o,k] ; else Wi[k-256,o]*sc0)
// ---------------------------------------------------------------------------
__global__ void fold1(const float* __restrict__ wr, const float* __restrict__ wi,
                      const float* __restrict__ iw, const float* __restrict__ n0w) {
    int idx = blockIdx.x * blockDim.x + threadIdx.x;
    if (idx >= BB * K1 * CC) return;
    int b = idx / (K1 * CC);
    int r = idx % (K1 * CC);
    int k = r / CC;
    int o = r % CC;
    int kk = (k < CC) ? k : k - CC;
    float sc = g_rstd0[b * CC + kk] * n0w[kk];
    float v;
    if (k < CC) v = wr[k * CC + o] * sc + iw[o * CC + k];
    else        v = wi[kk * CC + o] * sc;
    g_at1[idx] = __float2bfloat16_rn(v);
}

// bias1[b][o] = inner_b[o] + sum_k Wr[k,o]*sh0[b,k]
__global__ void fold1_bias(const float* __restrict__ wr, const float* __restrict__ ib,
                           const float* __restrict__ n0w, const float* __restrict__ n0b) {
    __shared__ float red[8];
    int o = blockIdx.x, b = blockIdx.y;
    int t = threadIdx.x;
    float m = g_mean0[b * CC + t], rs = g_rstd0[b * CC + t];
    float sh = n0b[t] - m * rs * n0w[t];
    float s = wr[t * CC + o] * sh;
    #pragma unroll
    for (int off = 16; off > 0; off >>= 1) s += __shfl_xor_sync(0xffffffffu, s, off);
    if ((t & 31) == 0) red[t >> 5] = s;
    __syncthreads();
    if (t == 0) {
        float S = 0.f;
        #pragma unroll
        for (int i = 0; i < 8; i++) S += red[i];
        g_bias1[b * CC + o] = ib[o] + S;
    }
}

// ---------------------------------------------------------------------------
// Fold 2 (norm1+FiLM folded inline): AT2[b][k][m] = w1[m,k]*scale[b,k]
// ---------------------------------------------------------------------------
__global__ void fold2(const float* __restrict__ w1,
                      const float* __restrict__ n1w, const float* __restrict__ gamma) {
    int idx = blockIdx.x * blockDim.x + threadIdx.x;
    if (idx >= BB * CC * HID) return;
    int b = idx / (CC * HID);
    int r = idx % (CC * HID);
    int k = r / HID;
    int m = r % HID;
    float scale = g_rstd1[b * CC + k] * n1w[k] * (1.0f + gamma[k]);
    g_at2[idx] = __float2bfloat16_rn(w1[m * CC + k] * scale);
}

// bias2[b][m] = b1[m] + sum_k w1[m,k]*shift[b,k]
__global__ void fold2_bias(const float* __restrict__ w1, const float* __restrict__ b1,
                           const float* __restrict__ n1w, const float* __restrict__ n1b,
                           const float* __restrict__ gamma, const float* __restrict__ beta) {
    __shared__ float red[8];
    int m = blockIdx.x, b = blockIdx.y;
    int t = threadIdx.x;
    float mm = g_mean1[b * CC + t], rs = g_rstd1[b * CC + t];
    float shift = (n1b[t] - mm * rs * n1w[t]) * (1.0f + gamma[t]) + beta[t];
    float s = w1[m * CC + t] * shift;
    #pragma unroll
    for (int off = 16; off > 0; off >>= 1) s += __shfl_xor_sync(0xffffffffu, s, off);
    if ((t & 31) == 0) red[t >> 5] = s;
    __syncthreads();
    if (t == 0) {
        float S = 0.f;
        #pragma unroll
        for (int i = 0; i < 8; i++) S += red[i];
        g_bias2[b * HID + m] = b1[m] + S;
    }
}

// w2t[k][m] = w2[m][k]
__global__ void pack_w2t(const float* __restrict__ w2) {
    int idx = blockIdx.x * blockDim.x + threadIdx.x;
    if (idx >= HID * CC) return;
    int k = idx / CC, m = idx % CC;
    g_w2t[idx] = __float2bfloat16_rn(w2[m * HID + k]);
}

// ---------------------------------------------------------------------------
// Tensor-core GEMM (mma.sync m16n8k16 bf16): C[m,n] = sum_k AT[k,m]*B[k,n]+bias
// 128x128x16 block tile, 8 warps (2x4), warp tile 64x32 = 4x4 mma frags.
// ldmatrix.x4.trans fragment loads. 3-stage cp.async ring.
// B rows from B1 (k<Ksplit) else B2. EPI 1: GELU ; EPI 2: +resid.
// OUTBF: store bf16, else fp32.
// ---------------------------------------------------------------------------
#define LDSM_X4_T(r0, r1, r2, r3, addr) \
    asm volatile("ldmatrix.sync.aligned.m8n8.x4.trans.shared.b16 {%0,%1,%2,%3}, [%4];" \
        : "=r"(r0), "=r"(r1), "=r"(r2), "=r"(r3) : "r"(addr))

__device__ __forceinline__ void mma_bf16(float4& d,
    uint32_t a0, uint32_t a1, uint32_t a2, uint32_t a3,
    uint32_t b0, uint32_t b1) {
    asm volatile(
        "mma.sync.aligned.m16n8k16.row.col.f32.bf16.bf16.f32 "
        "{%0,%1,%2,%3}, {%4,%5,%6,%7}, {%8,%9}, {%0,%1,%2,%3};\n"
        : "+f"(d.x), "+f"(d.y), "+f"(d.z), "+f"(d.w)
        : "r"(a0), "r"(a1), "r"(a2), "r"(a3), "r"(b0), "r"(b1));
}

template<int EPI, int OUTBF>
__global__ __launch_bounds__(256)
void mgemm(const bf16* __restrict__ AT, long aStride,
           const bf16* __restrict__ B1, long b1Stride,
           const bf16* __restrict__ B2, long b2Stride, int Ksplit,
           const float* __restrict__ bias, int biasStride,
           const float* __restrict__ resid,
           void* __restrict__ C, int M, int N, int K) {
    __shared__ bf16 As[3][16][136];
    __shared__ bf16 Bs[3][16][136];

    int tid  = threadIdx.x;
    int lane = tid & 31;
    int g    = lane >> 2;          // 0..7
    int tg   = lane & 3;           // 0..3
    int lrow = lane & 7;           // ldmatrix row
    int lmat = lane >> 3;          // ldmatrix matrix id
    int wid  = tid >> 5;
    int wm   = wid >> 2;           // 0..1
    int wn   = wid & 3;            // 0..3
    int mBase = wm * 64;
    int nBase = wn * 32;

    int m0 = blockIdx.y * 128;
    int n0 = blockIdx.x * 128;
    int bz = blockIdx.z;

    const bf16* ATp = AT + (size_t)bz * aStride;

    float4 acc[4][4];
    #pragma unroll
    for (int i = 0; i < 4; i++)
        #pragma unroll
        for (int j = 0; j < 4; j++) acc[i][j] = make_float4(0.f, 0.f, 0.f, 0.f);

    int r  = tid >> 4;            // 0..15 (k row)
    int c8 = (tid & 15) * 8;      // col within 128, 8 bf16 = 16B

    auto cpTile = [&](int k0, int st) {
        const bf16* ga = ATp + (size_t)(k0 + r) * M + m0 + c8;
        unsigned da = (unsigned)__cvta_generic_to_shared(&As[st][r][c8]);
        asm volatile("cp.async.cg.shared.global [%0], [%1], 16;\n" :: "r"(da), "l"(ga));
        int k = k0 + r;
        const bf16* gb = (k < Ksplit)
            ? B1 + (size_t)bz * b1Stride + (size_t)k * N + n0 + c8
            : B2 + (size_t)bz * b2Stride + (size_t)(k - Ksplit) * N + n0 + c8;
        unsigned db = (unsigned)__cvta_generic_to_shared(&Bs[st][r][c8]);
        asm volatile("cp.async.cg.shared.global [%0], [%1], 16;\n" :: "r"(db), "l"(gb));
        asm volatile("cp.async.commit_group;\n");
    };

    auto compute = [&](int st) {
        uint32_t a[4][4], b[4][2];
        #pragma unroll
        for (int i = 0; i < 4; i++) {
            unsigned pa = (unsigned)__cvta_generic_to_shared(
                &As[st][(lmat >> 1) * 8 + lrow][mBase + i * 16 + (lmat & 1) * 8]);
            LDSM_X4_T(a[i][0], a[i][1], a[i][2], a[i][3], pa);
        }
        #pragma unroll
        for (int jj = 0; jj < 2; jj++) {
            unsigned pb = (unsigned)__cvta_generic_to_shared(
                &Bs[st][(lmat & 1) * 8 + lrow][nBase + jj * 16 + (lmat >> 1) * 8]);
            LDSM_X4_T(b[2 * jj][0], b[2 * jj][1], b[2 * jj + 1][0], b[2 * jj + 1][1], pb);
        }
        #pragma unroll
        for (int i = 0; i < 4; i++)
            #pragma unroll
            for (int j = 0; j < 4; j++)
                mma_bf16(acc[i][j], a[i][0], a[i][1], a[i][2], a[i][3],
                         b[j][0], b[j][1]);
    };

    int T = K >> 4;
    cpTile(0, 0);
    cpTile(16, 1);
    for (int t = 0; t < T - 2; t++) {
        asm volatile("cp.async.wait_group 1;\n");
        __syncthreads();
        compute(t % 3);
        cpTile((t + 2) * 16, (t + 2) % 3);
    }
    asm volatile("cp.async.wait_group 1;\n");
    __syncthreads();
    compute((T - 2) % 3);
    asm volatile("cp.async.wait_group 0;\n");
    __syncthreads();
    compute((T - 1) % 3);

    // Epilogue
    float* Cf = (float*)C + (size_t)bz * M * N;
    bf16*  Cb = (bf16*)C  + (size_t)bz * M * N;
    #pragma unroll
    for (int i = 0; i < 4; i++) {
        int mr0 = m0 + mBase + i * 16 + g;
        int mr1 = mr0 + 8;
        float bv0 = bias[bz * biasStride + mr0];
        float bv1 = bias[bz * biasStride + mr1];
        #pragma unroll
        for (int j = 0; j < 4; j++) {
            int n = n0 + nBase + j * 8 + 2 * tg;
            float4 c = acc[i][j];
            float v0 = c.x + bv0, v1 = c.y + bv0;
            float v2 = c.z + bv1, v3 = c.w + bv1;
            if (EPI == 1) {
                v0 = 0.5f * v0 * (1.0f + erff(v0 * 0.70710678118654752f));
                v1 = 0.5f * v1 * (1.0f + erff(v1 * 0.70710678118654752f));
                v2 = 0.5f * v2 * (1.0f + erff(v2 * 0.70710678118654752f));
                v3 = 0.5f * v3 * (1.0f + erff(v3 * 0.70710678118654752f));
            }
            if (EPI == 2) {
                const float* rp = resid + (size_t)bz * M * N;
                float2 r0 = *(const float2*)&rp[(size_t)mr0 * N + n];
                float2 r1 = *(const float2*)&rp[(size_t)mr1 * N + n];
                v0 += r0.x; v1 += r0.y; v2 += r1.x; v3 += r1.y;
            }
            if (OUTBF) {
                *(__nv_bfloat162*)&Cb[(size_t)mr0 * N + n] = __floats2bfloat162_rn(v0, v1);
                *(__nv_bfloat162*)&Cb[(size_t)mr1 * N + n] = __floats2bfloat162_rn(v2, v3);
            } else {
                *(float2*)&Cf[(size_t)mr0 * N + n] = make_float2(v0, v1);
                *(float2*)&Cf[(size_t)mr1 * N + n] = make_float2(v2, v3);
            }
        }
    }
}

// ---------------------------------------------------------------------------
// Launch
// ---------------------------------------------------------------------------
extern "C" void kernel_launch(void* const* d_in, const int* in_sizes, int n_in,
                              void* d_out, int out_size) {
    const float* x      = (const float*)d_in[0];
    const float* gamma  = (const float*)d_in[1];
    const float* beta   = (const float*)d_in[2];
    const float* n0w    = (const float*)d_in[3];
    const float* n0b    = (const float*)d_in[4];
    const float* n1w    = (const float*)d_in[5];
    const float* n1b    = (const float*)d_in[6];
    const float* wr     = (const float*)d_in[7];
    const float* wi     = (const float*)d_in[8];
    const float* innerw = (const float*)d_in[9];
    const float* innerb = (const float*)d_in[10];
    const float* w1     = (const float*)d_in[11];
    const float* b1     = (const float*)d_in[12];
    const float* w2     = (const float*)d_in[13];
    const float* b2     = (const float*)d_in[14];
    float* out = (float*)d_out;

    bf16 *p_xr, *p_hx, *p_t0, *p_u, *p_at1, *p_at2, *p_w2t;
    float *p_b1f, *p_b2f, *p_mean0, *p_rstd0, *p_mean1, *p_rstd1;
    cudaGetSymbolAddress((void**)&p_xr,  g_xr);
    cudaGetSymbolAddress((void**)&p_hx,  g_hx);
    cudaGetSymbolAddress((void**)&p_t0,  g_t0);
    cudaGetSymbolAddress((void**)&p_u,   g_u);
    cudaGetSymbolAddress((void**)&p_at1, g_at1);
    cudaGetSymbolAddress((void**)&p_at2, g_at2);
    cudaGetSymbolAddress((void**)&p_w2t, g_w2t);
    cudaGetSymbolAddress((void**)&p_b1f, g_bias1);
    cudaGetSymbolAddress((void**)&p_b2f, g_bias2);
    cudaGetSymbolAddress((void**)&p_mean0, g_mean0);
    cudaGetSymbolAddress((void**)&p_rstd0, g_rstd0);
    cudaGetSymbolAddress((void**)&p_mean1, g_mean1);
    cudaGetSymbolAddress((void**)&p_rstd1, g_rstd1);

    // weight prep
    pack_w2t<<<(HID * CC + 255) / 256, 256>>>(w2);
    // inorm0 stats + bf16 copy of x
    inorm_stats_f32<<<BB * CC, 256>>>(x, p_mean0, p_rstd0, p_xr);
    // fold inorm0 into GEMM1 weights + bias
    fold1<<<(BB * K1 * CC + 255) / 256, 256>>>(wr, wi, innerw, n0w);
    fold1_bias<<<dim3(CC, BB), 256>>>(wr, innerb, n0w, n0b);
    // hilbert(x)
    hilbert_rows<<<(BB * CC * HH) / RPB, 240>>>(x);
    // GEMM1 + GELU: [256 x 512] x [xr ; hx] -> t0 (bf16)
    mgemm<1, 1><<<dim3(SS / 128, CC / 128, BB), 256>>>(
        p_at1, (long)K1 * CC, p_xr, (long)CC * SS, p_hx, (long)CC * SS, CC,
        p_b1f, CC, nullptr, p_t0, CC, SS, K1);
    // inorm1 stats + affine fold into mlp1
    inorm_stats_bf16<<<BB * CC, 256>>>(p_t0, p_mean1, p_rstd1);
    fold2<<<(BB * CC * HID + 255) / 256, 256>>>(w1, n1w, gamma);
    fold2_bias<<<dim3(HID, BB), 256>>>(w1, b1, n1w, n1b, gamma, beta);
    // mlp1 + GELU: [512 x 256] x t0 -> u (bf16)
    mgemm<1, 1><<<dim3(SS / 128, HID / 128, BB), 256>>>(
        p_at2, (long)CC * HID, p_t0, (long)CC * SS, p_t0, (long)CC * SS, CC,
        p_b2f, HID, nullptr, p_u, HID, SS, CC);
    // mlp2 + bias + residual: [256 x 512] x u + x -> out (fp32)
    mgemm<2, 0><<<dim3(SS / 128, CC / 128, BB), 256>>>(
        p_w2t, 0L, p_u, (long)HID * SS, p_u, (long)HID * SS, HID,
        b2, 0, x, out, CC, SS, HID);
}

// round 9
// speedup vs baseline: 6.2686x; 1.1003x over previous
#include <cuda_runtime.h>
#include <cuda_bf16.h>
#include <math.h>
#include <stdint.h>

// Problem constants
#define BB 2
#define CC 256
#define HH 120
#define WW 240
#define SS (HH*WW)          // 28800
#define HID 512
#define K1 512              // GEMM1 K: [x | hilbert(x)]
#define NROWS (BB*CC*HH)    // 61440 spatial rows of length 240

typedef __nv_bfloat16 bf16;

// ---------------------------------------------------------------------------
// Static scratch
// ---------------------------------------------------------------------------
__device__ bf16  g_xr  [(size_t)BB*CC*SS];     // bf16 copy of x
__device__ bf16  g_hx  [(size_t)BB*CC*SS];     // hilbert(x), bf16
__device__ bf16  g_t0  [(size_t)BB*CC*SS];     // post GEMM1+GELU
__device__ bf16  g_u   [(size_t)BB*HID*SS];    // post mlp1+GELU
__device__ bf16  g_at1 [BB*K1*CC];             // GEMM1 AT [b][k=512][m=256]
__device__ bf16  g_at2 [BB*CC*HID];            // mlp1  AT [b][k=256][m=512]
__device__ bf16  g_w2t [HID*CC];               // mlp2  AT [k=512][m=256]
__device__ bf16  g_ac  [WW*WW];                // circulant Hilbert matrix [w][w']
__device__ float g_bias1[BB*CC];
__device__ float g_bias2[BB*HID];
__device__ float g_mean0[BB*CC];
__device__ float g_rstd0[BB*CC];
__device__ float g_mean1[BB*CC];
__device__ float g_rstd1[BB*CC];

// ---------------------------------------------------------------------------
// Circulant Hilbert matrix: Ac[w][w'] = a[(w'-w) mod 240],
// a[d] = -(1/120)*cot(pi*d/240) for odd d, else 0.
// ---------------------------------------------------------------------------
__global__ void gen_ac() {
    int idx = blockIdx.x * blockDim.x + threadIdx.x;
    if (idx >= WW * WW) return;
    int w = idx / WW, wp = idx % WW;
    int d = wp - w; if (d < 0) d += WW;
    float v = 0.f;
    if (d & 1) {
        float ang = (float)d * (1.0f / 240.0f);
        v = -(1.0f / 120.0f) * (cospif(ang) / sinpif(ang));
    }
    g_ac[idx] = __float2bfloat16_rn(v);
}

// ---------------------------------------------------------------------------
// InstanceNorm statistics (one block per (b,c)) over fp32 input; emit bf16 copy
// ---------------------------------------------------------------------------
__global__ void inorm_stats_f32(const float* __restrict__ x,
                                float* __restrict__ mean, float* __restrict__ rstd,
                                bf16* __restrict__ xr) {
    __shared__ float ssum[8];
    __shared__ float ssq[8];
    int bc = blockIdx.x;
    const float4* p = (const float4*)(x + (size_t)bc * SS);
    __nv_bfloat162* pr = (__nv_bfloat162*)(xr + (size_t)bc * SS);
    int t = threadIdx.x;
    float s = 0.f, q = 0.f;
    for (int i = t; i < SS / 4; i += 256) {
        float4 v = p[i];
        s += v.x + v.y + v.z + v.w;
        q += v.x * v.x + v.y * v.y + v.z * v.z + v.w * v.w;
        pr[2 * i]     = __floats2bfloat162_rn(v.x, v.y);
        pr[2 * i + 1] = __floats2bfloat162_rn(v.z, v.w);
    }
    #pragma unroll
    for (int off = 16; off > 0; off >>= 1) {
        s += __shfl_xor_sync(0xffffffffu, s, off);
        q += __shfl_xor_sync(0xffffffffu, q, off);
    }
    int w = t >> 5, l = t & 31;
    if (l == 0) { ssum[w] = s; ssq[w] = q; }
    __syncthreads();
    if (t == 0) {
        float S = 0.f, Q = 0.f;
        #pragma unroll
        for (int i = 0; i < 8; i++) { S += ssum[i]; Q += ssq[i]; }
        float m = S * (1.0f / SS);
        float var = Q * (1.0f / SS) - m * m;
        mean[bc] = m;
        rstd[bc] = rsqrtf(var + 1e-5f);
    }
}

// Same but over bf16 input (t0), no emit
__global__ void inorm_stats_bf16(const bf16* __restrict__ x,
                                 float* __restrict__ mean, float* __restrict__ rstd) {
    __shared__ float ssum[8];
    __shared__ float ssq[8];
    int bc = blockIdx.x;
    const uint4* p = (const uint4*)(x + (size_t)bc * SS);
    int t = threadIdx.x;
    float s = 0.f, q = 0.f;
    for (int i = t; i < SS / 8; i += 256) {
        uint4 u = p[i];
        const __nv_bfloat162* h = (const __nv_bfloat162*)&u;
        #pragma unroll
        for (int j = 0; j < 4; j++) {
            float2 f = __bfloat1622float2(h[j]);
            s += f.x + f.y;
            q += f.x * f.x + f.y * f.y;
        }
    }
    #pragma unroll
    for (int off = 16; off > 0; off >>= 1) {
        s += __shfl_xor_sync(0xffffffffu, s, off);
        q += __shfl_xor_sync(0xffffffffu, q, off);
    }
    int w = t >> 5, l = t & 31;
    if (l == 0) { ssum[w] = s; ssq[w] = q; }
    __syncthreads();
    if (t == 0) {
        float S = 0.f, Q = 0.f;
        #pragma unroll
        for (int i = 0; i < 8; i++) { S += ssum[i]; Q += ssq[i]; }
        float m = S * (1.0f / SS);
        float var = Q * (1.0f / SS) - m * m;
        mean[bc] = m;
        rstd[bc] = rsqrtf(var + 1e-5f);
    }
}

// ---------------------------------------------------------------------------
// ldmatrix / mma primitives
// ---------------------------------------------------------------------------
#define LDSM_X4(r0, r1, r2, r3, addr) \
    asm volatile("ldmatrix.sync.aligned.m8n8.x4.shared.b16 {%0,%1,%2,%3}, [%4];" \
        : "=r"(r0), "=r"(r1), "=r"(r2), "=r"(r3) : "r"(addr))

#define LDSM_X4_T(r0, r1, r2, r3, addr) \
    asm volatile("ldmatrix.sync.aligned.m8n8.x4.trans.shared.b16 {%0,%1,%2,%3}, [%4];" \
        : "=r"(r0), "=r"(r1), "=r"(r2), "=r"(r3) : "r"(addr))

__device__ __forceinline__ void mma_bf16(float4& d,
    uint32_t a0, uint32_t a1, uint32_t a2, uint32_t a3,
    uint32_t b0, uint32_t b1) {
    asm volatile(
        "mma.sync.aligned.m16n8k16.row.col.f32.bf16.bf16.f32 "
        "{%0,%1,%2,%3}, {%4,%5,%6,%7}, {%8,%9}, {%0,%1,%2,%3};\n"
        : "+f"(d.x), "+f"(d.y), "+f"(d.z), "+f"(d.w)
        : "r"(a0), "r"(a1), "r"(a2), "r"(a3), "r"(b0), "r"(b1));
}

// ---------------------------------------------------------------------------
// Hilbert as tensor-core GEMM: hx[r, :] = xr[r, :] @ Ac   (per 128-row block)
// M=128 rows/block, N=240 (30 n-tiles, all in registers), K=240 (15 chunks).
// 3-stage cp.async ring. 8 warps, warp w owns rows [16w, 16w+16).
// ---------------------------------------------------------------------------
__global__ __launch_bounds__(256)
void hilbert_mma() {
    __shared__ bf16 Xs[3][128][24];    // 16-wide K chunk of X, pad 24 (48B stride)
    __shared__ bf16 Cs[3][16][248];    // 16-row chunk of Ac, pad 248

    int tid  = threadIdx.x;
    int lane = tid & 31;
    int wid  = tid >> 5;
    int lrow = lane & 7;
    int lmat = lane >> 3;
    int g    = lane >> 2;
    int tg   = lane & 3;
    size_t n0 = (size_t)blockIdx.x * 128;   // first global row

    float4 acc[30];
    #pragma unroll
    for (int j = 0; j < 30; j++) acc[j] = make_float4(0.f, 0.f, 0.f, 0.f);

    int xrow = tid >> 1, xhalf = tid & 1;

    auto cpTile = [&](int k0, int st) {
        // X chunk: 128 rows x 16 cols (2 x 16B per row) = 256 x 16B
        const bf16* gx = g_xr + (n0 + xrow) * WW + k0 + xhalf * 8;
        unsigned dx = (unsigned)__cvta_generic_to_shared(&Xs[st][xrow][xhalf * 8]);
        asm volatile("cp.async.cg.shared.global [%0], [%1], 16;\n" :: "r"(dx), "l"(gx));
        // Ac chunk: 16 rows x 240 cols = 16 x 30 x 16B = 480 chunks
        #pragma unroll
        for (int it = 0; it < 2; it++) {
            int idx = tid + it * 256;
            if (idx < 480) {
                int r = idx / 30, s = idx % 30;
                const bf16* ga = g_ac + (size_t)(k0 + r) * WW + s * 8;
                unsigned da = (unsigned)__cvta_generic_to_shared(&Cs[st][r][s * 8]);
                asm volatile("cp.async.cg.shared.global [%0], [%1], 16;\n" :: "r"(da), "l"(ga));
            }
        }
        asm volatile("cp.async.commit_group;\n");
    };

    auto compute = [&](int st) {
        uint32_t a0, a1, a2, a3;
        unsigned pa = (unsigned)__cvta_generic_to_shared(
            &Xs[st][wid * 16 + (lmat & 1) * 8 + lrow][(lmat >> 1) * 8]);
        LDSM_X4(a0, a1, a2, a3, pa);
        #pragma unroll
        for (int jj = 0; jj < 15; jj++) {
            uint32_t b0, b1, b2, b3;
            unsigned pb = (unsigned)__cvta_generic_to_shared(
                &Cs[st][(lmat & 1) * 8 + lrow][jj * 16 + (lmat >> 1) * 8]);
            LDSM_X4_T(b0, b1, b2, b3, pb);
            mma_bf16(acc[2 * jj],     a0, a1, a2, a3, b0, b1);
            mma_bf16(acc[2 * jj + 1], a0, a1, a2, a3, b2, b3);
        }
    };

    cpTile(0, 0);
    cpTile(16, 1);
    for (int t = 0; t < 13; t++) {
        asm volatile("cp.async.wait_group 1;\n");
        __syncthreads();
        compute(t % 3);
        cpTile((t + 2) * 16, (t + 2) % 3);
    }
    asm volatile("cp.async.wait_group 1;\n");
    __syncthreads();
    compute(13 % 3);
    asm volatile("cp.async.wait_group 0;\n");
    __syncthreads();
    compute(14 % 3);

    // Epilogue: rows r0=n0+16w+g, r1=r0+8; tile j -> cols j*8 + 2tg
    size_t r0 = n0 + wid * 16 + g;
    size_t r1 = r0 + 8;
    #pragma unroll
    for (int j = 0; j < 30; j++) {
        int n = j * 8 + 2 * tg;
        float4 c = acc[j];
        *(__nv_bfloat162*)&g_hx[r0 * WW + n] = __floats2bfloat162_rn(c.x, c.y);
        *(__nv_bfloat162*)&g_hx[r1 * WW + n] = __floats2bfloat162_rn(c.z, c.w);
    }
}

// ---------------------------------------------------------------------------
// Fold 1: AT1[b][k][o]  (k<256: Wr[k,o]*sc0 + iw[o,k] ; else Wi[k-256,o]*sc0)
// ---------------------------------------------------------------------------
__global__ void fold1(const float* __restrict__ wr, const float* __restrict__ wi,
                      const float* __restrict__ iw, const float* __restrict__ n0w) {
    int idx = blockIdx.x * blockDim.x + threadIdx.x;
    if (idx >= BB * K1 * CC) return;
    int b = idx / (K1 * CC);
    int r = idx % (K1 * CC);
    int k = r / CC;
    int o = r % CC;
    int kk = (k < CC) ? k : k - CC;
    float sc = g_rstd0[b * CC + kk] * n0w[kk];
    float v;
    if (k < CC) v = wr[k * CC + o] * sc + iw[o * CC + k];
    else        v = wi[kk * CC + o] * sc;
    g_at1[idx] = __float2bfloat16_rn(v);
}

// bias1[b][o] = inner_b[o] + sum_k Wr[k,o]*sh0[b,k]
// one block per b; thread = o; coalesced row sweeps of wr; shift cached in smem
__global__ void fold1_bias(const float* __restrict__ wr, const float* __restrict__ ib,
                           const float* __restrict__ n0w, const float* __restrict__ n0b) {
    __shared__ float sh[CC];
    int b = blockIdx.x;
    int o = threadIdx.x;
    {
        float m = g_mean0[b * CC + o], rs = g_rstd0[b * CC + o];
        sh[o] = n0b[o] - m * rs * n0w[o];
    }
    __syncthreads();
    float s = 0.f;
    #pragma unroll 8
    for (int k = 0; k < CC; k++)
        s += wr[k * CC + o] * sh[k];
    g_bias1[b * CC + o] = ib[o] + s;
}

// ---------------------------------------------------------------------------
// Fold 2 (norm1+FiLM folded inline): AT2[b][k][m] = w1[m,k]*scale[b,k]
// ---------------------------------------------------------------------------
__global__ void fold2(const float* __restrict__ w1,
                      const float* __restrict__ n1w, const float* __restrict__ gamma) {
    int idx = blockIdx.x * blockDim.x + threadIdx.x;
    if (idx >= BB * CC * HID) return;
    int b = idx / (CC * HID);
    int r = idx % (CC * HID);
    int k = r / HID;
    int m = r % HID;
    float scale = g_rstd1[b * CC + k] * n1w[k] * (1.0f + gamma[k]);
    g_at2[idx] = __float2bfloat16_rn(w1[m * CC + k] * scale);
}

// bias2[b][m] = b1[m] + sum_k w1[m,k]*shift[b,k]
// warp-per-m (coalesced lane-over-k), 8 warps/block, grid (HID/8, BB)
__global__ void fold2_bias(const float* __restrict__ w1, const float* __restrict__ b1,
                           const float* __restrict__ n1w, const float* __restrict__ n1b,
                           const float* __restrict__ gamma, const float* __restrict__ beta) {
    int b = blockIdx.y;
    int m = blockIdx.x * 8 + (threadIdx.x >> 5);
    int lane = threadIdx.x & 31;
    float s = 0.f;
    #pragma unroll
    for (int i = 0; i < CC; i += 32) {
        int k = i + lane;
        float mm = g_mean1[b * CC + k], rs = g_rstd1[b * CC + k];
        float shift = (n1b[k] - mm * rs * n1w[k]) * (1.0f + gamma[k]) + beta[k];
        s += w1[m * CC + k] * shift;
    }
    #pragma unroll
    for (int off = 16; off > 0; off >>= 1) s += __shfl_xor_sync(0xffffffffu, s, off);
    if (lane == 0) g_bias2[b * HID + m] = b1[m] + s;
}

// w2t[k][m] = w2[m][k]
__global__ void pack_w2t(const float* __restrict__ w2) {
    int idx = blockIdx.x * blockDim.x + threadIdx.x;
    if (idx >= HID * CC) return;
    int k = idx / CC, m = idx % CC;
    g_w2t[idx] = __float2bfloat16_rn(w2[m * HID + k]);
}

// ---------------------------------------------------------------------------
// Tensor-core GEMM (mma.sync m16n8k16 bf16): C[m,n] = sum_k AT[k,m]*B[k,n]+bias
// 128x128x16 block tile, 8 warps (2x4), warp tile 64x32 = 4x4 mma frags.
// ldmatrix.x4.trans fragment loads. 3-stage cp.async ring.
// B rows from B1 (k<Ksplit) else B2. EPI 1: GELU ; EPI 2: +resid.
// OUTBF: store bf16, else fp32.
// ---------------------------------------------------------------------------
template<int EPI, int OUTBF>
__global__ __launch_bounds__(256)
void mgemm(const bf16* __restrict__ AT, long aStride,
           const bf16* __restrict__ B1, long b1Stride,
           const bf16* __restrict__ B2, long b2Stride, int Ksplit,
           const float* __restrict__ bias, int biasStride,
           const float* __restrict__ resid,
           void* __restrict__ C, int M, int N, int K) {
    __shared__ bf16 As[3][16][136];
    __shared__ bf16 Bs[3][16][136];

    int tid  = threadIdx.x;
    int lane = tid & 31;
    int g    = lane >> 2;          // 0..7
    int tg   = lane & 3;           // 0..3
    int lrow = lane & 7;           // ldmatrix row
    int lmat = lane >> 3;          // ldmatrix matrix id
    int wid  = tid >> 5;
    int wm   = wid >> 2;           // 0..1
    int wn   = wid & 3;            // 0..3
    int mBase = wm * 64;
    int nBase = wn * 32;

    int m0 = blockIdx.y * 128;
    int n0 = blockIdx.x * 128;
    int bz = blockIdx.z;

    const bf16* ATp = AT + (size_t)bz * aStride;

    float4 acc[4][4];
    #pragma unroll
    for (int i = 0; i < 4; i++)
        #pragma unroll
        for (int j = 0; j < 4; j++) acc[i][j] = make_float4(0.f, 0.f, 0.f, 0.f);

    int r  = tid >> 4;            // 0..15 (k row)
    int c8 = (tid & 15) * 8;      // col within 128, 8 bf16 = 16B

    auto cpTile = [&](int k0, int st) {
        const bf16* ga = ATp + (size_t)(k0 + r) * M + m0 + c8;
        unsigned da = (unsigned)__cvta_generic_to_shared(&As[st][r][c8]);
        asm volatile("cp.async.cg.shared.global [%0], [%1], 16;\n" :: "r"(da), "l"(ga));
        int k = k0 + r;
        const bf16* gb = (k < Ksplit)
            ? B1 + (size_t)bz * b1Stride + (size_t)k * N + n0 + c8
            : B2 + (size_t)bz * b2Stride + (size_t)(k - Ksplit) * N + n0 + c8;
        unsigned db = (unsigned)__cvta_generic_to_shared(&Bs[st][r][c8]);
        asm volatile("cp.async.cg.shared.global [%0], [%1], 16;\n" :: "r"(db), "l"(gb));
        asm volatile("cp.async.commit_group;\n");
    };

    auto compute = [&](int st) {
        uint32_t a[4][4], b[4][2];
        #pragma unroll
        for (int i = 0; i < 4; i++) {
            unsigned pa = (unsigned)__cvta_generic_to_shared(
                &As[st][(lmat >> 1) * 8 + lrow][mBase + i * 16 + (lmat & 1) * 8]);
            LDSM_X4_T(a[i][0], a[i][1], a[i][2], a[i][3], pa);
        }
        #pragma unroll
        for (int jj = 0; jj < 2; jj++) {
            unsigned pb = (unsigned)__cvta_generic_to_shared(
                &Bs[st][(lmat & 1) * 8 + lrow][nBase + jj * 16 + (lmat >> 1) * 8]);
            LDSM_X4_T(b[2 * jj][0], b[2 * jj][1], b[2 * jj + 1][0], b[2 * jj + 1][1], pb);
        }
        #pragma unroll
        for (int i = 0; i < 4; i++)
            #pragma unroll
            for (int j = 0; j < 4; j++)
                mma_bf16(acc[i][j], a[i][0], a[i][1], a[i][2], a[i][3],
                         b[j][0], b[j][1]);
    };

    int T = K >> 4;
    cpTile(0, 0);
    cpTile(16, 1);
    for (int t = 0; t < T - 2; t++) {
        asm volatile("cp.async.wait_group 1;\n");
        __syncthreads();
        compute(t % 3);
        cpTile((t + 2) * 16, (t + 2) % 3);
    }
    asm volatile("cp.async.wait_group 1;\n");
    __syncthreads();
    compute((T - 2) % 3);
    asm volatile("cp.async.wait_group 0;\n");
    __syncthreads();
    compute((T - 1) % 3);

    // Epilogue
    float* Cf = (float*)C + (size_t)bz * M * N;
    bf16*  Cb = (bf16*)C  + (size_t)bz * M * N;
    #pragma unroll
    for (int i = 0; i < 4; i++) {
        int mr0 = m0 + mBase + i * 16 + g;
        int mr1 = mr0 + 8;
        float bv0 = bias[bz * biasStride + mr0];
        float bv1 = bias[bz * biasStride + mr1];
        #pragma unroll
        for (int j = 0; j < 4; j++) {
            int n = n0 + nBase + j * 8 + 2 * tg;
            float4 c = acc[i][j];
            float v0 = c.x + bv0, v1 = c.y + bv0;
            float v2 = c.z + bv1, v3 = c.w + bv1;
            if (EPI == 1) {
                v0 = 0.5f * v0 * (1.0f + erff(v0 * 0.70710678118654752f));
                v1 = 0.5f * v1 * (1.0f + erff(v1 * 0.70710678118654752f));
                v2 = 0.5f * v2 * (1.0f + erff(v2 * 0.70710678118654752f));
                v3 = 0.5f * v3 * (1.0f + erff(v3 * 0.70710678118654752f));
            }
            if (EPI == 2) {
                const float* rp = resid + (size_t)bz * M * N;
                float2 r0 = *(const float2*)&rp[(size_t)mr0 * N + n];
                float2 r1 = *(const float2*)&rp[(size_t)mr1 * N + n];
                v0 += r0.x; v1 += r0.y; v2 += r1.x; v3 += r1.y;
            }
            if (OUTBF) {
                *(__nv_bfloat162*)&Cb[(size_t)mr0 * N + n] = __floats2bfloat162_rn(v0, v1);
                *(__nv_bfloat162*)&Cb[(size_t)mr1 * N + n] = __floats2bfloat162_rn(v2, v3);
            } else {
                *(float2*)&Cf[(size_t)mr0 * N + n] = make_float2(v0, v1);
                *(float2*)&Cf[(size_t)mr1 * N + n] = make_float2(v2, v3);
            }
        }
    }
}

// ---------------------------------------------------------------------------
// Launch
// ---------------------------------------------------------------------------
extern "C" void kernel_launch(void* const* d_in, const int* in_sizes, int n_in,
                              void* d_out, int out_size) {
    const float* x      = (const float*)d_in[0];
    const float* gamma  = (const float*)d_in[1];
    const float* beta   = (const float*)d_in[2];
    const float* n0w    = (const float*)d_in[3];
    const float* n0b    = (const float*)d_in[4];
    const float* n1w    = (const float*)d_in[5];
    const float* n1b    = (const float*)d_in[6];
    const float* wr     = (const float*)d_in[7];
    const float* wi     = (const float*)d_in[8];
    const float* innerw = (const float*)d_in[9];
    const float* innerb = (const float*)d_in[10];
    const float* w1     = (const float*)d_in[11];
    const float* b1     = (const float*)d_in[12];
    const float* w2     = (const float*)d_in[13];
    const float* b2     = (const float*)d_in[14];
    float* out = (float*)d_out;

    bf16 *p_xr, *p_hx, *p_t0, *p_u, *p_at1, *p_at2, *p_w2t;
    float *p_b1f, *p_b2f, *p_mean0, *p_rstd0, *p_mean1, *p_rstd1;
    cudaGetSymbolAddress((void**)&p_xr,  g_xr);
    cudaGetSymbolAddress((void**)&p_hx,  g_hx);
    cudaGetSymbolAddress((void**)&p_t0,  g_t0);
    cudaGetSymbolAddress((void**)&p_u,   g_u);
    cudaGetSymbolAddress((void**)&p_at1, g_at1);
    cudaGetSymbolAddress((void**)&p_at2, g_at2);
    cudaGetSymbolAddress((void**)&p_w2t, g_w2t);
    cudaGetSymbolAddress((void**)&p_b1f, g_bias1);
    cudaGetSymbolAddress((void**)&p_b2f, g_bias2);
    cudaGetSymbolAddress((void**)&p_mean0, g_mean0);
    cudaGetSymbolAddress((void**)&p_rstd0, g_rstd0);
    cudaGetSymbolAddress((void**)&p_mean1, g_mean1);
    cudaGetSymbolAddress((void**)&p_rstd1, g_rstd1);

    // weight prep + circulant matrix
    pack_w2t<<<(HID * CC + 255) / 256, 256>>>(w2);
    gen_ac<<<(WW * WW + 255) / 256, 256>>>();
    // inorm0 stats + bf16 copy of x
    inorm_stats_f32<<<BB * CC, 256>>>(x, p_mean0, p_rstd0, p_xr);
    // fold inorm0 into GEMM1 weights + bias
    fold1<<<(BB * K1 * CC + 255) / 256, 256>>>(wr, wi, innerw, n0w);
    fold1_bias<<<BB, 256>>>(wr, innerb, n0w, n0b);
    // hilbert(x) via tensor cores: hx = xr @ Ac
    hilbert_mma<<<NROWS / 128, 256>>>();
    // GEMM1 + GELU: [256 x 512] x [xr ; hx] -> t0 (bf16)
    mgemm<1, 1><<<dim3(SS / 128, CC / 128, BB), 256>>>(
        p_at1, (long)K1 * CC, p_xr, (long)CC * SS, p_hx, (long)CC * SS, CC,
        p_b1f, CC, nullptr, p_t0, CC, SS, K1);
    // inorm1 stats + affine fold into mlp1
    inorm_stats_bf16<<<BB * CC, 256>>>(p_t0, p_mean1, p_rstd1);
    fold2<<<(BB * CC * HID + 255) / 256, 256>>>(w1, n1w, gamma);
    fold2_bias<<<dim3(HID / 8, BB), 256>>>(w1, b1, n1w, n1b, gamma, beta);
    // mlp1 + GELU: [512 x 256] x t0 -> u (bf16)
    mgemm<1, 1><<<dim3(SS / 128, HID / 128, BB), 256>>>(
        p_at2, (long)CC * HID, p_t0, (long)CC * SS, p_t0, (long)CC * SS, CC,
        p_b2f, HID, nullptr, p_u, HID, SS, CC);
    // mlp2 + bias + residual: [256 x 512] x u + x -> out (fp32)
    mgemm<2, 0><<<dim3(SS / 128, CC / 128, BB), 256>>>(
        p_w2t, 0L, p_u, (long)HID * SS, p_u, (long)HID * SS, HID,
        b2, 0, x, out, CC, SS, HID);
}